// round 1
// baseline (speedup 1.0000x reference)
#include <cuda_runtime.h>
#include <math.h>

#define NN 20000
#define NG 400
#define KNB 12
#define NE 240000
#define NL 4

// ---------------- static device scratch (no allocations allowed) ----------------
__device__ float g_temb[NG * 128];
__device__ float g_h[NN * 128];
__device__ float g_X0[NN * 160];      // [z | species_emb]
__device__ float g_X[NN * 256];       // [h | t_nodes]
__device__ float g_Y[NN * 384];       // [h | m_i | t_nodes]
__device__ float g_P[NN * 256];       // [P_src | P_dst]
__device__ float g_M[NE * 128];       // per-edge message m
__device__ float g_gate[NE];
__device__ float g_u[NN * 128];
__device__ float g_Wp[256 * 256];     // packed layer weight for node-level pre-GEMM
__device__ float g_bp[256];
__device__ float g_shift[NN * 3];

__device__ __forceinline__ float silu_f(float x) { return x / (1.0f + __expf(-x)); }

// ---------------- time embedding MLP: [G,128] ----------------
__global__ void temb_kernel(const float* __restrict__ t,
                            const float* __restrict__ W1, const float* __restrict__ b1,
                            const float* __restrict__ W2, const float* __restrict__ b2) {
    int g = blockIdx.x;
    int tid = threadIdx.x;           // 128 threads
    __shared__ float e[128];
    __shared__ float hid[256];
    float tv = t[g];
    if (tid < 64) {
        float f = expf(-(float)tid * (logf(10000.0f) / 63.0f));
        float a = tv * f;
        e[tid]      = sinf(a);
        e[tid + 64] = cosf(a);
    }
    __syncthreads();
    for (int j = tid; j < 256; j += 128) {
        float s = b1[j];
        #pragma unroll 4
        for (int k = 0; k < 128; k++) s = fmaf(e[k], W1[k * 256 + j], s);
        hid[j] = silu_f(s);
    }
    __syncthreads();
    float s = b2[tid];
    #pragma unroll 4
    for (int k = 0; k < 256; k++) s = fmaf(hid[k], W2[k * 128 + tid], s);
    g_temb[g * 128 + tid] = s;
}

// ---------------- per-node prep: X0, t-parts of X/Y, zero shift ----------------
__global__ void prep_kernel(const float* __restrict__ z, const int* __restrict__ species,
                            const int* __restrict__ batch, const float* __restrict__ spemb) {
    int n = blockIdx.x;
    int tid = threadIdx.x;           // 128
    g_X0[n * 160 + tid] = z[n * 128 + tid];
    if (tid < 32) g_X0[n * 160 + 128 + tid] = spemb[species[n] * 32 + tid];
    float tt = g_temb[batch[n] * 128 + tid];
    g_X[n * 256 + 128 + tid] = tt;
    g_Y[n * 384 + 256 + tid] = tt;
    if (tid < 3) g_shift[n * 3 + tid] = 0.f;
}

// ---------------- pack layer-l eW1 into [256,256] Wp and bias bp ----------------
// pre(e) = P_src[src] + P_dst[dst] + dist_sq*wc, with
//   P[:, :128]  = h@eW1[0:128]   + t@eW1[257:385] + eb1
//   P[:, 128:]  = h@eW1[128:256]
__global__ void build_wp_kernel(const float* __restrict__ eW1, const float* __restrict__ eb1, int l) {
    const float* W = eW1 + (size_t)l * 385 * 128;
    int idx = blockIdx.x * 256 + threadIdx.x;   // 256 blocks x 256 threads = 65536
    int k = idx >> 8, j = idx & 255;
    float v;
    if (j < 128) {
        v = (k < 128) ? W[k * 128 + j] : W[(257 + (k - 128)) * 128 + j];
    } else {
        v = (k < 128) ? W[(128 + k) * 128 + (j - 128)] : 0.f;
    }
    g_Wp[k * 256 + j] = v;
    if (idx < 256) g_bp[idx] = (idx < 128) ? eb1[l * 128 + idx] : 0.f;
}

// ---------------- generic tiled GEMM: C[M,Nout] = epi(A[M,K] @ W[K,Nout] + b) ----------------
// BM=64, BN=128, BK=32, 256 threads, thread tile 8x4.
// EDGEA: A row e is built on the fly: silu(P[src,k] + P[dst,128+k] + dist_sq*wc[k])
// GATE : epilogue = silu then dot with cw2 -> gate_out[row] (no C store)
template <bool EDGEA, bool SILU, bool RES, bool DUAL, bool GATE>
__global__ __launch_bounds__(256)
void gemm_kernel(const float* __restrict__ A, int ldA,
                 const float* __restrict__ W, int ldW,
                 const float* __restrict__ bias,
                 float* __restrict__ C, int ldC,
                 float* __restrict__ C2, int ldC2,
                 int M, int Kdim,
                 const float* __restrict__ Rsrc,
                 const int* __restrict__ esrc, const int* __restrict__ edst,
                 const float* __restrict__ coords,
                 const float* __restrict__ P, const float* __restrict__ wc,
                 const float* __restrict__ cw2, float* __restrict__ gate_out) {
    const int BM = 64, BN = 128, BK = 32;
    int m0 = blockIdx.x * BM;
    int bn0 = blockIdx.y * BN;
    int tid = threadIdx.x;
    int lane = tid & 31;
    int trow = tid >> 5;             // 0..7

    __shared__ __align__(16) float As[BK][BM + 1];
    __shared__ __align__(16) float Ws[BK][BN];
    __shared__ int s_src[BM];
    __shared__ int s_dst[BM];
    __shared__ float s_ds[BM];
    __shared__ float s_cw2[BN];

    if (EDGEA) {
        if (tid < BM) {
            int e = m0 + tid;
            int s = esrc[e], d = edst[e];
            s_src[tid] = s; s_dst[tid] = d;
            float dx = coords[s * 3 + 0] - coords[d * 3 + 0];
            float dy = coords[s * 3 + 1] - coords[d * 3 + 1];
            float dz = coords[s * 3 + 2] - coords[d * 3 + 2];
            s_ds[tid] = dx * dx + dy * dy + dz * dz;
        }
    }
    if (GATE) {
        if (tid < BN) s_cw2[tid] = cw2[tid];
    }

    float acc[8][4];
    #pragma unroll
    for (int i = 0; i < 8; i++)
        #pragma unroll
        for (int j = 0; j < 4; j++) acc[i][j] = 0.f;

    for (int k0 = 0; k0 < Kdim; k0 += BK) {
        __syncthreads();
        // ---- load A tile (64 x 32) ----
        #pragma unroll
        for (int i = 0; i < 2; i++) {
            int idx = tid + i * 256;       // 0..511
            int r = idx >> 3;              // 0..63
            int c4 = idx & 7;              // 0..7
            int kg = k0 + c4 * 4;
            float4 v;
            if (EDGEA) {
                int s = s_src[r], d = s_dst[r];
                float ds = s_ds[r];
                float4 ps = *(const float4*)(P + (size_t)s * 256 + kg);
                float4 pd = *(const float4*)(P + (size_t)d * 256 + 128 + kg);
                float4 w  = *(const float4*)(wc + kg);
                v.x = silu_f(ps.x + pd.x + ds * w.x);
                v.y = silu_f(ps.y + pd.y + ds * w.y);
                v.z = silu_f(ps.z + pd.z + ds * w.z);
                v.w = silu_f(ps.w + pd.w + ds * w.w);
            } else {
                int row = m0 + r;
                if (row < M) v = *(const float4*)(A + (size_t)row * ldA + kg);
                else         v = make_float4(0.f, 0.f, 0.f, 0.f);
            }
            As[c4 * 4 + 0][r] = v.x;
            As[c4 * 4 + 1][r] = v.y;
            As[c4 * 4 + 2][r] = v.z;
            As[c4 * 4 + 3][r] = v.w;
        }
        // ---- load W tile (32 x 128) ----
        #pragma unroll
        for (int i = 0; i < 4; i++) {
            int idx = tid + i * 256;       // 0..1023
            int rr = idx >> 5;             // 0..31
            int c4 = idx & 31;             // 0..31
            float4 v = *(const float4*)(W + (size_t)(k0 + rr) * ldW + bn0 + c4 * 4);
            *(float4*)(&Ws[rr][c4 * 4]) = v;
        }
        __syncthreads();
        // ---- compute ----
        #pragma unroll
        for (int kk = 0; kk < BK; kk++) {
            float a[8];
            #pragma unroll
            for (int i = 0; i < 8; i++) a[i] = As[kk][trow * 8 + i];
            float4 w = *(const float4*)(&Ws[kk][lane * 4]);
            #pragma unroll
            for (int i = 0; i < 8; i++) {
                acc[i][0] = fmaf(a[i], w.x, acc[i][0]);
                acc[i][1] = fmaf(a[i], w.y, acc[i][1]);
                acc[i][2] = fmaf(a[i], w.z, acc[i][2]);
                acc[i][3] = fmaf(a[i], w.w, acc[i][3]);
            }
        }
    }

    // ---- epilogue ----
    float4 bv = make_float4(0.f, 0.f, 0.f, 0.f);
    if (bias) bv = *(const float4*)(bias + bn0 + lane * 4);
    int col = bn0 + lane * 4;
    #pragma unroll
    for (int i = 0; i < 8; i++) {
        int row = m0 + trow * 8 + i;
        if (row >= M) continue;   // uniform per warp (trow fixed)
        float v0 = acc[i][0] + bv.x;
        float v1 = acc[i][1] + bv.y;
        float v2 = acc[i][2] + bv.z;
        float v3 = acc[i][3] + bv.w;
        if (SILU) { v0 = silu_f(v0); v1 = silu_f(v1); v2 = silu_f(v2); v3 = silu_f(v3); }
        if constexpr (GATE) {
            float p = v0 * s_cw2[lane * 4 + 0] + v1 * s_cw2[lane * 4 + 1]
                    + v2 * s_cw2[lane * 4 + 2] + v3 * s_cw2[lane * 4 + 3];
            #pragma unroll
            for (int off = 16; off; off >>= 1) p += __shfl_xor_sync(0xffffffffu, p, off);
            if (lane == 0) gate_out[row] = p;
        } else {
            if constexpr (RES) {
                const float* r = Rsrc + (size_t)row * 128 + col;
                v0 += r[0]; v1 += r[1]; v2 += r[2]; v3 += r[3];
            }
            float4 o = make_float4(v0, v1, v2, v3);
            *(float4*)(C + (size_t)row * ldC + col) = o;
            if constexpr (DUAL) *(float4*)(C2 + (size_t)row * ldC2 + col) = o;
        }
    }
}

// ---------------- per-node aggregation: m_i, shift accumulation, Y refresh ----------------
__global__ void aggregate_kernel(const int* __restrict__ esrc, const int* __restrict__ edst,
                                 const float* __restrict__ coords) {
    int n = blockIdx.x;
    int tid = threadIdx.x;           // 128
    const float* Mrow = g_M + (size_t)n * KNB * 128;
    float mi = 0.f;
    #pragma unroll
    for (int e = 0; e < KNB; e++) mi += Mrow[e * 128 + tid];
    g_Y[n * 384 + 128 + tid] = mi;
    g_Y[n * 384 + tid] = g_h[n * 128 + tid];
    if (tid < 32) {
        float sx = 0.f, sy = 0.f, sz = 0.f;
        if (tid < KNB) {
            int e = n * KNB + tid;
            int s = esrc[e], d = edst[e];
            float dx = coords[s * 3 + 0] - coords[d * 3 + 0];
            float dy = coords[s * 3 + 1] - coords[d * 3 + 1];
            float dz = coords[s * 3 + 2] - coords[d * 3 + 2];
            float ds = dx * dx + dy * dy + dz * dz;
            float gt = g_gate[e] / sqrtf(ds + 1e-8f);
            sx = dx * gt; sy = dy * gt; sz = dz * gt;
        }
        #pragma unroll
        for (int off = 16; off; off >>= 1) {
            sx += __shfl_xor_sync(0xffffffffu, sx, off);
            sy += __shfl_xor_sync(0xffffffffu, sy, off);
            sz += __shfl_xor_sync(0xffffffffu, sz, off);
        }
        if (tid == 0) {
            g_shift[n * 3 + 0] += sx;
            g_shift[n * 3 + 1] += sy;
            g_shift[n * 3 + 2] += sz;
        }
    }
}

// ---------------- output: [total_shift (N*3) | h (N*128)] ----------------
__global__ void finalize_kernel(float* __restrict__ out) {
    int n = blockIdx.x, tid = threadIdx.x;   // 128
    out[NN * 3 + n * 128 + tid] = g_h[n * 128 + tid];
    if (tid < 3) out[n * 3 + tid] = g_shift[n * 3 + tid];
}

extern "C" void kernel_launch(void* const* d_in, const int* in_sizes, int n_in,
                              void* d_out, int out_size) {
    const float* z      = (const float*)d_in[0];
    const float* t      = (const float*)d_in[1];
    const float* coords = (const float*)d_in[2];
    const int*   species= (const int*)d_in[3];
    const int*   batch  = (const int*)d_in[4];
    const int*   esrc   = (const int*)d_in[5];
    const int*   edst   = (const int*)d_in[6];
    const float* spemb  = (const float*)d_in[7];
    const float* tmW1   = (const float*)d_in[8];
    const float* tmb1   = (const float*)d_in[9];
    const float* tmW2   = (const float*)d_in[10];
    const float* tmb2   = (const float*)d_in[11];
    const float* neW    = (const float*)d_in[12];
    const float* neb    = (const float*)d_in[13];
    const float* eW1    = (const float*)d_in[14];
    const float* eb1    = (const float*)d_in[15];
    const float* eW2    = (const float*)d_in[16];
    const float* eb2    = (const float*)d_in[17];
    const float* cW1    = (const float*)d_in[18];
    const float* cb1    = (const float*)d_in[19];
    const float* cW2    = (const float*)d_in[20];
    const float* nW1    = (const float*)d_in[21];
    const float* nb1    = (const float*)d_in[22];
    const float* nW2    = (const float*)d_in[23];
    const float* nb2    = (const float*)d_in[24];

    float *pX0, *pX, *pY, *pP, *pM, *pU, *pH, *pWp, *pBp, *pGate;
    cudaGetSymbolAddress((void**)&pX0, g_X0);
    cudaGetSymbolAddress((void**)&pX,  g_X);
    cudaGetSymbolAddress((void**)&pY,  g_Y);
    cudaGetSymbolAddress((void**)&pP,  g_P);
    cudaGetSymbolAddress((void**)&pM,  g_M);
    cudaGetSymbolAddress((void**)&pU,  g_u);
    cudaGetSymbolAddress((void**)&pH,  g_h);
    cudaGetSymbolAddress((void**)&pWp, g_Wp);
    cudaGetSymbolAddress((void**)&pBp, g_bp);
    cudaGetSymbolAddress((void**)&pGate, g_gate);

    dim3 blk(256);
    const int GN = (NN + 63) / 64;   // 313 node-row blocks
    const int GE = NE / 64;          // 3750 edge-row blocks

    temb_kernel<<<NG, 128>>>(t, tmW1, tmb1, tmW2, tmb2);
    prep_kernel<<<NN, 128>>>(z, species, batch, spemb);

    // h0 = [z|sp] @ ne_W + ne_b ; dual-store into g_h and g_X[:, :128]
    gemm_kernel<false, false, false, true, false><<<dim3(GN, 1), blk>>>(
        pX0, 160, neW, 128, neb, pH, 128, pX, 256, NN, 160,
        nullptr, nullptr, nullptr, nullptr, nullptr, nullptr, nullptr, nullptr);

    for (int l = 0; l < NL; l++) {
        build_wp_kernel<<<256, 256>>>(eW1, eb1, l);
        // P = [h|t] @ Wp + bp   ([N,256] -> [N,256])
        gemm_kernel<false, false, false, false, false><<<dim3(GN, 2), blk>>>(
            pX, 256, pWp, 256, pBp, pP, 256, nullptr, 0, NN, 256,
            nullptr, nullptr, nullptr, nullptr, nullptr, nullptr, nullptr, nullptr);
        // m = silu( silu(pre) @ eW2 + eb2 )   (fused gather-A edge GEMM)
        gemm_kernel<true, true, false, false, false><<<dim3(GE, 1), blk>>>(
            nullptr, 0, eW2 + (size_t)l * 128 * 128, 128, eb2 + l * 128,
            pM, 128, nullptr, 0, NE, 128,
            nullptr, esrc, edst, coords, pP,
            eW1 + (size_t)l * 385 * 128 + 256 * 128, nullptr, nullptr);
        // gate = silu(m @ cW1 + cb1) . cW2
        gemm_kernel<false, true, false, false, true><<<dim3(GE, 1), blk>>>(
            pM, 128, cW1 + (size_t)l * 128 * 128, 128, cb1 + l * 128,
            nullptr, 0, nullptr, 0, NE, 128,
            nullptr, nullptr, nullptr, nullptr, nullptr, nullptr,
            cW2 + l * 128, pGate);
        // segment sums (contiguous dst groups of 12) + shift accumulation + Y refresh
        aggregate_kernel<<<NN, 128>>>(esrc, edst, coords);
        // u = silu([h|m_i|t] @ nW1 + nb1)
        gemm_kernel<false, true, false, false, false><<<dim3(GN, 1), blk>>>(
            pY, 384, nW1 + (size_t)l * 384 * 128, 128, nb1 + l * 128,
            pU, 128, nullptr, 0, NN, 384,
            nullptr, nullptr, nullptr, nullptr, nullptr, nullptr, nullptr, nullptr);
        // h = h + u @ nW2 + nb2 ; dual-store into g_h and g_X[:, :128]
        gemm_kernel<false, false, true, true, false><<<dim3(GN, 1), blk>>>(
            pU, 128, nW2 + (size_t)l * 128 * 128, 128, nb2 + l * 128,
            pH, 128, pX, 256, NN, 128,
            pH, nullptr, nullptr, nullptr, nullptr, nullptr, nullptr, nullptr);
    }

    finalize_kernel<<<NN, 128>>>((float*)d_out);
}

// round 3
// speedup vs baseline: 1.8017x; 1.8017x over previous
#include <cuda_runtime.h>
#include <math.h>
#include <stdint.h>

#define NN 20000
#define NG 400
#define KNB 12
#define NE 240000
#define NL 4

// ---- packed weight region offsets (floats) ----
#define PK_EW2 0
#define PK_CW1 65536
#define PK_NW2 131072
#define PK_NW1 196608
#define PK_NE  393216
#define PK_WP  413696
#define PK_TOTAL 675840

// ---- static device scratch ----
__device__ float g_temb[NG * 128];
__device__ float g_h[NN * 128];
__device__ float g_X0[NN * 160];
__device__ float g_X[NN * 256];
__device__ float g_Y[NN * 384];
__device__ float g_P[NN * 256];
__device__ float g_M[NE * 128];
__device__ float g_gate[NE];
__device__ float g_u[NN * 128];
__device__ float g_Wp4[NL * 256 * 256];
__device__ float g_packW[PK_TOTAL];
__device__ float g_shift[NN * 3];
__device__ float g_zero128[128];   // stays zero

__device__ __forceinline__ float silu_f(float x) { return x / (1.0f + __expf(-x)); }
__device__ __forceinline__ float to_tf32(float x) {
    float r; asm("cvt.rna.tf32.f32 %0, %1;" : "=f"(r) : "f"(x)); return r;
}

// warp-level tf32 MMA: D[16x8] += A[16x8] * B[8x8]
__device__ __forceinline__ void mma_tf32(float c[4], uint32_t a0, uint32_t a1,
                                         uint32_t a2, uint32_t a3,
                                         uint32_t b0, uint32_t b1) {
    asm volatile(
        "mma.sync.aligned.m16n8k8.row.col.f32.tf32.tf32.f32 "
        "{%0,%1,%2,%3}, {%4,%5,%6,%7}, {%8,%9}, {%0,%1,%2,%3};"
        : "+f"(c[0]), "+f"(c[1]), "+f"(c[2]), "+f"(c[3])
        : "r"(a0), "r"(a1), "r"(a2), "r"(a3), "r"(b0), "r"(b1));
}

// ================= small kernels =================
__global__ void temb_kernel(const float* __restrict__ t,
                            const float* __restrict__ W1, const float* __restrict__ b1,
                            const float* __restrict__ W2, const float* __restrict__ b2) {
    int g = blockIdx.x, tid = threadIdx.x;   // 128
    __shared__ float e[128];
    __shared__ float hid[256];
    float tv = t[g];
    if (tid < 64) {
        float f = expf(-(float)tid * (logf(10000.0f) / 63.0f));
        float a = tv * f;
        e[tid] = sinf(a); e[tid + 64] = cosf(a);
    }
    __syncthreads();
    for (int j = tid; j < 256; j += 128) {
        float s = b1[j];
        #pragma unroll 4
        for (int k = 0; k < 128; k++) s = fmaf(e[k], W1[k * 256 + j], s);
        hid[j] = silu_f(s);
    }
    __syncthreads();
    float s = b2[tid];
    #pragma unroll 4
    for (int k = 0; k < 256; k++) s = fmaf(hid[k], W2[k * 128 + tid], s);
    g_temb[g * 128 + tid] = s;
}

__global__ void prep_kernel(const float* __restrict__ z, const int* __restrict__ species,
                            const int* __restrict__ batch, const float* __restrict__ spemb) {
    int n = blockIdx.x, tid = threadIdx.x;   // 128
    g_X0[n * 160 + tid] = z[n * 128 + tid];
    if (tid < 32) g_X0[n * 160 + 128 + tid] = spemb[species[n] * 32 + tid];
    float tt = g_temb[batch[n] * 128 + tid];
    g_X[n * 256 + 128 + tid] = tt;
    g_Y[n * 384 + 256 + tid] = tt;
    if (tid < 3) g_shift[n * 3 + tid] = 0.f;
}

// Wp4[l]: eW1[l] folded to node-level [256,256]
__global__ void build_wp4_kernel(const float* __restrict__ eW1) {
    int l = blockIdx.y;
    const float* W = eW1 + (size_t)l * 385 * 128;
    int idx = blockIdx.x * 256 + threadIdx.x;
    int k = idx >> 8, j = idx & 255;
    float v;
    if (j < 128) v = (k < 128) ? W[k * 128 + j] : W[(257 + (k - 128)) * 128 + j];
    else         v = (k < 128) ? W[(128 + k) * 128 + (j - 128)] : 0.f;
    g_Wp4[(size_t)l * 65536 + idx] = v;
}

// pack all weights into fragment-major tf32 images.
// Per 32-K block (4096 floats): idx = ((nf*4+ks)*32+lane)*2+pair
//   k = kb*32 + ks*8 + (lane&3) + pair*4 ; n = nf*8 + (lane>>2)
__global__ void pack_kernel(const float* __restrict__ eW2, const float* __restrict__ cW1,
                            const float* __restrict__ nW2, const float* __restrict__ nW1,
                            const float* __restrict__ neW) {
    int f = blockIdx.y;
    int i = blockIdx.x * 256 + threadIdx.x;
    int kb, rr, dstbase;
    const float* src = nullptr;
    int ldn = 128, koff = 0, noff = 0;
    if (f <= 2) {
        if (i >= 65536) return;
        const float* W = (f == 0) ? eW2 : ((f == 1) ? cW1 : nW2);
        int l = i >> 14, r14 = i & 16383;
        kb = r14 >> 12; rr = r14 & 4095;
        src = W + (size_t)l * 16384;
        dstbase = ((f == 0) ? PK_EW2 : ((f == 1) ? PK_CW1 : PK_NW2)) + l * 16384;
    } else if (f == 3) {
        if (i >= 196608) return;
        int l = i / 49152, r = i % 49152;
        kb = r >> 12; rr = r & 4095;
        src = nW1 + (size_t)l * 49152;
        dstbase = PK_NW1 + l * 49152;
    } else if (f == 4) {
        if (i >= 20480) return;
        kb = i >> 12; rr = i & 4095;
        src = neW;
        dstbase = PK_NE;
    } else {
        if (i >= 262144) return;
        int l = i >> 16, r = i & 65535, slab = r >> 15, r2 = r & 32767;
        kb = r2 >> 12; rr = r2 & 4095;
        src = g_Wp4 + (size_t)l * 65536;
        ldn = 256; noff = slab * 128;
        dstbase = PK_WP + (l * 2 + slab) * 32768;
    }
    int pair = rr & 1;
    int lane = (rr >> 1) & 31;
    int ks   = (rr >> 6) & 3;
    int nf   = rr >> 8;
    int k = kb * 32 + ks * 8 + (lane & 3) + pair * 4 + koff;
    int n = nf * 8 + (lane >> 2) + noff;
    g_packW[dstbase + kb * 4096 + rr] = to_tf32(src[(size_t)k * ldn + n]);
}

// ================= node GEMM via mma.sync =================
// C[M,128] = epi(A[M,K] @ Wpk + b); K = Kb*32; 256 thr, 8 warps x 16 rows
#define NODE_SMEM (8832 * 4)
template <bool SILU, bool RES, bool DUAL>
__global__ void __launch_bounds__(256, 2) mma_node(
    const float* __restrict__ A, int ldA,
    const float* __restrict__ Wpk, const float* __restrict__ bias,
    float* __restrict__ C, int ldC, float* __restrict__ C2, int ldC2,
    int M, int Kb, const float* __restrict__ Rsrc) {
    extern __shared__ float sm[];
    float* As = sm;                 // 128 x 36
    float* Bs = sm + 4608;          // 4096
    float* s_bias = sm + 8704;      // 128
    int tid = threadIdx.x, w = tid >> 5, lane = tid & 31;
    if (tid < 128) s_bias[tid] = bias[tid];
    int m0 = blockIdx.x * 128;

    float acc[16][4];
    #pragma unroll
    for (int nf = 0; nf < 16; nf++)
        #pragma unroll
        for (int j = 0; j < 4; j++) acc[nf][j] = 0.f;

    for (int kb = 0; kb < Kb; kb++) {
        #pragma unroll
        for (int i = 0; i < 4; i++) {
            int idx = tid + i * 256;
            int r = idx >> 3, c4 = idx & 7;
            int grow = m0 + r;
            float4 v = make_float4(0.f, 0.f, 0.f, 0.f);
            if (grow < M) {
                float4 tt = *(const float4*)(A + (size_t)grow * ldA + kb * 32 + c4 * 4);
                v.x = to_tf32(tt.x); v.y = to_tf32(tt.y);
                v.z = to_tf32(tt.z); v.w = to_tf32(tt.w);
            }
            *(float4*)(As + r * 36 + c4 * 4) = v;
        }
        #pragma unroll
        for (int j = 0; j < 4; j++)
            ((float4*)Bs)[tid + j * 256] = ((const float4*)(Wpk + (size_t)kb * 4096))[tid + j * 256];
        __syncthreads();
        #pragma unroll
        for (int ks = 0; ks < 4; ks++) {
            const float* ap = As + (w * 16 + (lane >> 2)) * 36 + ks * 8 + (lane & 3);
            uint32_t a0 = __float_as_uint(ap[0]);
            uint32_t a1 = __float_as_uint(ap[8 * 36]);
            uint32_t a2 = __float_as_uint(ap[4]);
            uint32_t a3 = __float_as_uint(ap[8 * 36 + 4]);
            #pragma unroll
            for (int nf = 0; nf < 16; nf++) {
                float2 b = *(const float2*)(Bs + ((nf * 4 + ks) * 32 + lane) * 2);
                mma_tf32(acc[nf], a0, a1, a2, a3,
                         __float_as_uint(b.x), __float_as_uint(b.y));
            }
        }
        __syncthreads();
    }

    int r0 = w * 16 + (lane >> 2);
    int row0 = m0 + r0, row1 = row0 + 8;
    #pragma unroll
    for (int nf = 0; nf < 16; nf++) {
        int col = nf * 8 + (lane & 3) * 2;
        float v0 = acc[nf][0] + s_bias[col];
        float v1 = acc[nf][1] + s_bias[col + 1];
        float v2 = acc[nf][2] + s_bias[col];
        float v3 = acc[nf][3] + s_bias[col + 1];
        if (SILU) { v0 = silu_f(v0); v1 = silu_f(v1); v2 = silu_f(v2); v3 = silu_f(v3); }
        if (row0 < M) {
            if (RES) {
                float2 r = *(const float2*)(Rsrc + (size_t)row0 * 128 + col);
                v0 += r.x; v1 += r.y;
            }
            *(float2*)(C + (size_t)row0 * ldC + col) = make_float2(v0, v1);
            if (DUAL) *(float2*)(C2 + (size_t)row0 * ldC2 + col) = make_float2(v0, v1);
        }
        if (row1 < M) {
            if (RES) {
                float2 r = *(const float2*)(Rsrc + (size_t)row1 * 128 + col);
                v2 += r.x; v3 += r.y;
            }
            *(float2*)(C + (size_t)row1 * ldC + col) = make_float2(v2, v3);
            if (DUAL) *(float2*)(C2 + (size_t)row1 * ldC2 + col) = make_float2(v2, v3);
        }
    }
}

// ================= fused edge kernel =================
// A pitch 132; 128 edges/CTA; two back-to-back GEMMs
#define EDGE_SMEM (21888 * 4)
__device__ __forceinline__ void edge_gemm(const float* As, float* Bs,
                                          const float* __restrict__ Wpk,
                                          float acc[16][4], int tid, int w, int lane) {
    for (int kb = 0; kb < 4; kb++) {
        #pragma unroll
        for (int j = 0; j < 4; j++)
            ((float4*)Bs)[tid + j * 256] = ((const float4*)(Wpk + (size_t)kb * 4096))[tid + j * 256];
        __syncthreads();
        #pragma unroll
        for (int ks = 0; ks < 4; ks++) {
            const float* ap = As + (w * 16 + (lane >> 2)) * 132 + kb * 32 + ks * 8 + (lane & 3);
            uint32_t a0 = __float_as_uint(ap[0]);
            uint32_t a1 = __float_as_uint(ap[8 * 132]);
            uint32_t a2 = __float_as_uint(ap[4]);
            uint32_t a3 = __float_as_uint(ap[8 * 132 + 4]);
            #pragma unroll
            for (int nf = 0; nf < 16; nf++) {
                float2 b = *(const float2*)(Bs + ((nf * 4 + ks) * 32 + lane) * 2);
                mma_tf32(acc[nf], a0, a1, a2, a3,
                         __float_as_uint(b.x), __float_as_uint(b.y));
            }
        }
        __syncthreads();
    }
}

__global__ void __launch_bounds__(256, 2) mma_edge(
    const int* __restrict__ esrc, const int* __restrict__ edst,
    const float* __restrict__ coords, const float* __restrict__ P,
    const float* __restrict__ wc, const float* __restrict__ eb2,
    const float* __restrict__ w2pk, const float* __restrict__ c1pk,
    const float* __restrict__ cb1, const float* __restrict__ cw2) {
    extern __shared__ float sm[];
    float* As   = sm;                    // 128 x 132 = 16896
    float* Bs   = sm + 16896;            // 4096
    int* s_src  = (int*)(sm + 20992);
    int* s_dst  = (int*)(sm + 21120);
    float* s_ds = sm + 21248;
    float* s_wc = sm + 21376;
    float* s_eb2= sm + 21504;
    float* s_cb1= sm + 21632;
    float* s_cw2= sm + 21760;
    int tid = threadIdx.x, w = tid >> 5, lane = tid & 31;

    if (tid < 128) {
        int e = blockIdx.x * 128 + tid;
        int s = esrc[e], d = edst[e];
        s_src[tid] = s; s_dst[tid] = d;
        float dx = coords[s * 3 + 0] - coords[d * 3 + 0];
        float dy = coords[s * 3 + 1] - coords[d * 3 + 1];
        float dz = coords[s * 3 + 2] - coords[d * 3 + 2];
        s_ds[tid] = dx * dx + dy * dy + dz * dz;
        s_wc[tid] = wc[tid];
        s_eb2[tid] = eb2[tid];
        s_cb1[tid] = cb1[tid];
        s_cw2[tid] = cw2[tid];
    }
    __syncthreads();

    // ---- build A = tf32(silu(P_src + P_dst + ds*wc)) ----
    #pragma unroll
    for (int i = 0; i < 16; i++) {
        int idx = tid + i * 256;
        int r = idx >> 5, c4 = idx & 31;
        int s = s_src[r], d = s_dst[r];
        float ds = s_ds[r];
        float4 ps = *(const float4*)(P + (size_t)s * 256 + c4 * 4);
        float4 pd = *(const float4*)(P + (size_t)d * 256 + 128 + c4 * 4);
        float4 wv = *(const float4*)(s_wc + c4 * 4);
        float4 v;
        v.x = to_tf32(silu_f(ps.x + pd.x + ds * wv.x));
        v.y = to_tf32(silu_f(ps.y + pd.y + ds * wv.y));
        v.z = to_tf32(silu_f(ps.z + pd.z + ds * wv.z));
        v.w = to_tf32(silu_f(ps.w + pd.w + ds * wv.w));
        *(float4*)(As + r * 132 + c4 * 4) = v;
    }
    __syncthreads();

    float acc[16][4];
    #pragma unroll
    for (int nf = 0; nf < 16; nf++)
        #pragma unroll
        for (int j = 0; j < 4; j++) acc[nf][j] = 0.f;

    // ---- GEMM 1: pre @ eW2 ----
    edge_gemm(As, Bs, w2pk, acc, tid, w, lane);

    // ---- epilogue 1: m = silu(.+eb2) -> g_M + As (tf32) ----
    int r0 = w * 16 + (lane >> 2);
    int e0 = blockIdx.x * 128 + r0;
    #pragma unroll
    for (int nf = 0; nf < 16; nf++) {
        int col = nf * 8 + (lane & 3) * 2;
        float m0 = silu_f(acc[nf][0] + s_eb2[col]);
        float m1 = silu_f(acc[nf][1] + s_eb2[col + 1]);
        float m2 = silu_f(acc[nf][2] + s_eb2[col]);
        float m3 = silu_f(acc[nf][3] + s_eb2[col + 1]);
        *(float2*)(g_M + (size_t)e0 * 128 + col)       = make_float2(m0, m1);
        *(float2*)(g_M + (size_t)(e0 + 8) * 128 + col) = make_float2(m2, m3);
        *(float2*)(As + r0 * 132 + col)       = make_float2(to_tf32(m0), to_tf32(m1));
        *(float2*)(As + (r0 + 8) * 132 + col) = make_float2(to_tf32(m2), to_tf32(m3));
        acc[nf][0] = 0.f; acc[nf][1] = 0.f; acc[nf][2] = 0.f; acc[nf][3] = 0.f;
    }
    __syncthreads();

    // ---- GEMM 2: m @ cW1 ----
    edge_gemm(As, Bs, c1pk, acc, tid, w, lane);

    // ---- epilogue 2: gate = silu(.+cb1) . cw2 ----
    float g0 = 0.f, g1 = 0.f;
    #pragma unroll
    for (int nf = 0; nf < 16; nf++) {
        int col = nf * 8 + (lane & 3) * 2;
        g0 += silu_f(acc[nf][0] + s_cb1[col]) * s_cw2[col]
            + silu_f(acc[nf][1] + s_cb1[col + 1]) * s_cw2[col + 1];
        g1 += silu_f(acc[nf][2] + s_cb1[col]) * s_cw2[col]
            + silu_f(acc[nf][3] + s_cb1[col + 1]) * s_cw2[col + 1];
    }
    g0 += __shfl_xor_sync(0xffffffffu, g0, 1);
    g0 += __shfl_xor_sync(0xffffffffu, g0, 2);
    g1 += __shfl_xor_sync(0xffffffffu, g1, 1);
    g1 += __shfl_xor_sync(0xffffffffu, g1, 2);
    if ((lane & 3) == 0) {
        g_gate[e0] = g0;
        g_gate[e0 + 8] = g1;
    }
}

// ================= aggregation / finalize =================
__global__ void aggregate_kernel(const int* __restrict__ esrc, const int* __restrict__ edst,
                                 const float* __restrict__ coords) {
    int n = blockIdx.x, tid = threadIdx.x;   // 128
    const float* Mrow = g_M + (size_t)n * KNB * 128;
    float mi = 0.f;
    #pragma unroll
    for (int e = 0; e < KNB; e++) mi += Mrow[e * 128 + tid];
    g_Y[n * 384 + 128 + tid] = mi;
    g_Y[n * 384 + tid] = g_h[n * 128 + tid];
    if (tid < 32) {
        float sx = 0.f, sy = 0.f, sz = 0.f;
        if (tid < KNB) {
            int e = n * KNB + tid;
            int s = esrc[e], d = edst[e];
            float dx = coords[s * 3 + 0] - coords[d * 3 + 0];
            float dy = coords[s * 3 + 1] - coords[d * 3 + 1];
            float dz = coords[s * 3 + 2] - coords[d * 3 + 2];
            float dd = dx * dx + dy * dy + dz * dz;
            float gt = g_gate[e] / sqrtf(dd + 1e-8f);
            sx = dx * gt; sy = dy * gt; sz = dz * gt;
        }
        #pragma unroll
        for (int off = 16; off; off >>= 1) {
            sx += __shfl_xor_sync(0xffffffffu, sx, off);
            sy += __shfl_xor_sync(0xffffffffu, sy, off);
            sz += __shfl_xor_sync(0xffffffffu, sz, off);
        }
        if (tid == 0) {
            g_shift[n * 3 + 0] += sx;
            g_shift[n * 3 + 1] += sy;
            g_shift[n * 3 + 2] += sz;
        }
    }
}

__global__ void finalize_kernel(float* __restrict__ out) {
    int n = blockIdx.x, tid = threadIdx.x;
    out[NN * 3 + n * 128 + tid] = g_h[n * 128 + tid];
    if (tid < 3) out[n * 3 + tid] = g_shift[n * 3 + tid];
}

// ================= host =================
extern "C" void kernel_launch(void* const* d_in, const int* in_sizes, int n_in,
                              void* d_out, int out_size) {
    const float* z      = (const float*)d_in[0];
    const float* t      = (const float*)d_in[1];
    const float* coords = (const float*)d_in[2];
    const int*   species= (const int*)d_in[3];
    const int*   batch  = (const int*)d_in[4];
    const int*   esrc   = (const int*)d_in[5];
    const int*   edst   = (const int*)d_in[6];
    const float* spemb  = (const float*)d_in[7];
    const float* tmW1   = (const float*)d_in[8];
    const float* tmb1   = (const float*)d_in[9];
    const float* tmW2   = (const float*)d_in[10];
    const float* tmb2   = (const float*)d_in[11];
    const float* neW    = (const float*)d_in[12];
    const float* neb    = (const float*)d_in[13];
    const float* eW1    = (const float*)d_in[14];
    const float* eb1    = (const float*)d_in[15];
    const float* eW2    = (const float*)d_in[16];
    const float* eb2    = (const float*)d_in[17];
    const float* cW1    = (const float*)d_in[18];
    const float* cb1    = (const float*)d_in[19];
    const float* cW2    = (const float*)d_in[20];
    const float* nW1    = (const float*)d_in[21];
    const float* nb1    = (const float*)d_in[22];
    const float* nW2    = (const float*)d_in[23];
    const float* nb2    = (const float*)d_in[24];

    float *pX0, *pX, *pY, *pP, *pU, *pH, *pPk, *pZero;
    cudaGetSymbolAddress((void**)&pX0,  g_X0);
    cudaGetSymbolAddress((void**)&pX,   g_X);
    cudaGetSymbolAddress((void**)&pY,   g_Y);
    cudaGetSymbolAddress((void**)&pP,   g_P);
    cudaGetSymbolAddress((void**)&pU,   g_u);
    cudaGetSymbolAddress((void**)&pH,   g_h);
    cudaGetSymbolAddress((void**)&pPk,  g_packW);
    cudaGetSymbolAddress((void**)&pZero, g_zero128);

    cudaFuncSetAttribute(mma_edge, cudaFuncAttributeMaxDynamicSharedMemorySize, EDGE_SMEM);

    const int MT = (NN + 127) / 128;   // 157

    temb_kernel<<<NG, 128>>>(t, tmW1, tmb1, tmW2, tmb2);
    prep_kernel<<<NN, 128>>>(z, species, batch, spemb);
    build_wp4_kernel<<<dim3(256, NL), 256>>>(eW1);
    pack_kernel<<<dim3(1024, 6), 256>>>(eW2, cW1, nW2, nW1, neW);

    // h0 = [z|sp] @ neW + neb  (dual-store h, X[:, :128])
    mma_node<false, false, true><<<MT, 256, NODE_SMEM>>>(
        pX0, 160, pPk + PK_NE, neb, pH, 128, pX, 256, NN, 5, nullptr);

    for (int l = 0; l < NL; l++) {
        // P = [h|t] @ Wp (two 128-col slabs)
        mma_node<false, false, false><<<MT, 256, NODE_SMEM>>>(
            pX, 256, pPk + PK_WP + (l * 2 + 0) * 32768, eb1 + l * 128,
            pP, 256, nullptr, 0, NN, 8, nullptr);
        mma_node<false, false, false><<<MT, 256, NODE_SMEM>>>(
            pX, 256, pPk + PK_WP + (l * 2 + 1) * 32768, pZero,
            pP + 128, 256, nullptr, 0, NN, 8, nullptr);
        // fused edge: m + gate
        mma_edge<<<NE / 128, 256, EDGE_SMEM>>>(
            esrc, edst, coords, pP,
            eW1 + (size_t)l * 385 * 128 + 256 * 128, eb2 + l * 128,
            pPk + PK_EW2 + l * 16384, pPk + PK_CW1 + l * 16384,
            cb1 + l * 128, cW2 + l * 128);
        aggregate_kernel<<<NN, 128>>>(esrc, edst, coords);
        // u = silu([h|m_i|t] @ nW1 + nb1)
        mma_node<true, false, false><<<MT, 256, NODE_SMEM>>>(
            pY, 384, pPk + PK_NW1 + l * 49152, nb1 + l * 128,
            pU, 128, nullptr, 0, NN, 12, nullptr);
        // h = h + u @ nW2 + nb2  (dual-store h, X[:, :128])
        mma_node<false, true, true><<<MT, 256, NODE_SMEM>>>(
            pU, 128, pPk + PK_NW2 + l * 16384, nb2 + l * 128,
            pH, 128, pX, 256, NN, 4, pH);
    }

    finalize_kernel<<<NN, 128>>>((float*)d_out);
}

// round 4
// speedup vs baseline: 1.8927x; 1.0505x over previous
#include <cuda_runtime.h>
#include <math.h>
#include <stdint.h>

#define NN 20000
#define NG 400
#define KNB 12
#define NE 240000
#define NL 4

// ---- packed weight region offsets (floats) ----
#define PK_EW2 0
#define PK_CW1 65536
#define PK_NW2 131072
#define PK_NW1 196608
#define PK_NE  393216
#define PK_WP  413696
#define PK_TOTAL 675840

// ---- static device scratch ----
__device__ float g_temb[NG * 128];
__device__ float g_h[NN * 128];
__device__ float g_X0[NN * 160];
__device__ float g_X[NN * 256];
__device__ float g_Y[NN * 384];
__device__ float g_P[NN * 256];
__device__ float g_M[NE * 128];
__device__ float g_gate[NE];
__device__ float g_u[NN * 128];
__device__ float g_Wp4[NL * 256 * 256];
__device__ float g_packW[PK_TOTAL];
__device__ float g_biasP[NL * 256];
__device__ float g_shift[NN * 3];

__device__ __forceinline__ float silu_f(float x) { return x / (1.0f + __expf(-x)); }
__device__ __forceinline__ float to_tf32(float x) {
    float r; asm("cvt.rna.tf32.f32 %0, %1;" : "=f"(r) : "f"(x)); return r;
}

__device__ __forceinline__ void mma_tf32(float c[4], uint32_t a0, uint32_t a1,
                                         uint32_t a2, uint32_t a3,
                                         uint32_t b0, uint32_t b1) {
    asm volatile(
        "mma.sync.aligned.m16n8k8.row.col.f32.tf32.tf32.f32 "
        "{%0,%1,%2,%3}, {%4,%5,%6,%7}, {%8,%9}, {%0,%1,%2,%3};"
        : "+f"(c[0]), "+f"(c[1]), "+f"(c[2]), "+f"(c[3])
        : "r"(a0), "r"(a1), "r"(a2), "r"(a3), "r"(b0), "r"(b1));
}

__device__ __forceinline__ void cp16(uint32_t saddr, const void* g) {
    asm volatile("cp.async.ca.shared.global [%0], [%1], 16;" :: "r"(saddr), "l"(g));
}
#define CP_COMMIT() asm volatile("cp.async.commit_group;" ::: "memory")
#define CP_WAIT1()  asm volatile("cp.async.wait_group 1;" ::: "memory")
#define CP_WAIT0()  asm volatile("cp.async.wait_group 0;" ::: "memory")

// ================= small kernels =================
__global__ void temb_kernel(const float* __restrict__ t,
                            const float* __restrict__ W1, const float* __restrict__ b1,
                            const float* __restrict__ W2, const float* __restrict__ b2) {
    int g = blockIdx.x, tid = threadIdx.x;   // 128
    __shared__ float e[128];
    __shared__ float hid[256];
    float tv = t[g];
    if (tid < 64) {
        float f = expf(-(float)tid * (logf(10000.0f) / 63.0f));
        float a = tv * f;
        e[tid] = sinf(a); e[tid + 64] = cosf(a);
    }
    __syncthreads();
    for (int j = tid; j < 256; j += 128) {
        float s = b1[j];
        #pragma unroll 4
        for (int k = 0; k < 128; k++) s = fmaf(e[k], W1[k * 256 + j], s);
        hid[j] = silu_f(s);
    }
    __syncthreads();
    float s = b2[tid];
    #pragma unroll 4
    for (int k = 0; k < 256; k++) s = fmaf(hid[k], W2[k * 128 + tid], s);
    g_temb[g * 128 + tid] = s;
}

__global__ void prep_kernel(const float* __restrict__ z, const int* __restrict__ species,
                            const int* __restrict__ batch, const float* __restrict__ spemb) {
    int n = blockIdx.x, tid = threadIdx.x;   // 128
    g_X0[n * 160 + tid] = z[n * 128 + tid];
    if (tid < 32) g_X0[n * 160 + 128 + tid] = spemb[species[n] * 32 + tid];
    float tt = g_temb[batch[n] * 128 + tid];
    g_X[n * 256 + 128 + tid] = tt;
    g_Y[n * 384 + 256 + tid] = tt;
    if (tid < 3) g_shift[n * 3 + tid] = 0.f;
}

__global__ void build_wp4_kernel(const float* __restrict__ eW1, const float* __restrict__ eb1) {
    int l = blockIdx.y;
    const float* W = eW1 + (size_t)l * 385 * 128;
    int idx = blockIdx.x * 256 + threadIdx.x;
    int k = idx >> 8, j = idx & 255;
    float v;
    if (j < 128) v = (k < 128) ? W[k * 128 + j] : W[(257 + (k - 128)) * 128 + j];
    else         v = (k < 128) ? W[(128 + k) * 128 + (j - 128)] : 0.f;
    g_Wp4[(size_t)l * 65536 + idx] = v;
    if (idx < 256) g_biasP[l * 256 + idx] = (idx < 128) ? eb1[l * 128 + idx] : 0.f;
}

// pack weights into fragment-major tf32 images (per 32-K block of 4096 floats:
// idx = ((nf*4+ks)*32+lane)*2+pair ; k = kb*32+ks*8+(lane&3)+pair*4 ; n = nf*8+(lane>>2))
__global__ void pack_kernel(const float* __restrict__ eW2, const float* __restrict__ cW1,
                            const float* __restrict__ nW2, const float* __restrict__ nW1,
                            const float* __restrict__ neW) {
    int f = blockIdx.y;
    int i = blockIdx.x * 256 + threadIdx.x;
    int kb, rr, dstbase;
    const float* src = nullptr;
    int ldn = 128, noff = 0;
    if (f <= 2) {
        if (i >= 65536) return;
        const float* W = (f == 0) ? eW2 : ((f == 1) ? cW1 : nW2);
        int l = i >> 14, r14 = i & 16383;
        kb = r14 >> 12; rr = r14 & 4095;
        src = W + (size_t)l * 16384;
        dstbase = ((f == 0) ? PK_EW2 : ((f == 1) ? PK_CW1 : PK_NW2)) + l * 16384;
    } else if (f == 3) {
        if (i >= 196608) return;
        int l = i / 49152, r = i % 49152;
        kb = r >> 12; rr = r & 4095;
        src = nW1 + (size_t)l * 49152;
        dstbase = PK_NW1 + l * 49152;
    } else if (f == 4) {
        if (i >= 20480) return;
        kb = i >> 12; rr = i & 4095;
        src = neW;
        dstbase = PK_NE;
    } else {
        if (i >= 262144) return;
        int l = i >> 16, r = i & 65535, slab = r >> 15, r2 = r & 32767;
        kb = r2 >> 12; rr = r2 & 4095;
        src = g_Wp4 + (size_t)l * 65536;
        ldn = 256; noff = slab * 128;
        dstbase = PK_WP + (l * 2 + slab) * 32768;
    }
    int pair = rr & 1;
    int lane = (rr >> 1) & 31;
    int ks   = (rr >> 6) & 3;
    int nf   = rr >> 8;
    int k = kb * 32 + ks * 8 + (lane & 3) + pair * 4;
    int n = nf * 8 + (lane >> 2) + noff;
    g_packW[dstbase + kb * 4096 + rr] = to_tf32(src[(size_t)k * ldn + n]);
}

// ================= pipelined node GEMM =================
// C[M, NS*128] = epi(A[M,K] @ [W0|W1] + bias); K = Kb*32
// smem: As[4608] | Bs[2][NS*4096] | bias[NS*128]
template <int NS, bool SILU, bool RES, bool DUAL>
__global__ void __launch_bounds__(256) mma_node(
    const float* __restrict__ A, int ldA,
    const float* __restrict__ W0, const float* __restrict__ W1,
    const float* __restrict__ bias,
    float* __restrict__ C, int ldC, float* __restrict__ C2, int ldC2,
    int M, int Kb, const float* __restrict__ Rsrc) {
    extern __shared__ float sm[];
    float* As = sm;
    float* Bs = sm + 4608;
    float* s_bias = Bs + 2 * 4096 * NS;
    int tid = threadIdx.x, w = tid >> 5, lane = tid & 31;
    for (int i = tid; i < NS * 128; i += 256) s_bias[i] = bias[i];
    int m0 = blockIdx.x * 128;
    uint32_t bs_sm = (uint32_t)__cvta_generic_to_shared(Bs);

    float acc[NS][16][4];
    #pragma unroll
    for (int s = 0; s < NS; s++)
        #pragma unroll
        for (int nf = 0; nf < 16; nf++)
            #pragma unroll
            for (int j = 0; j < 4; j++) acc[s][nf][j] = 0.f;

    float4 av[4];
    auto ldA_regs = [&](int kb) {
        #pragma unroll
        for (int i = 0; i < 4; i++) {
            int idx = tid + i * 256;
            int r = idx >> 3, c4 = idx & 7;
            int row = m0 + r;
            if (row < M) av[i] = *(const float4*)(A + (size_t)row * ldA + kb * 32 + c4 * 4);
            else av[i] = make_float4(0.f, 0.f, 0.f, 0.f);
        }
    };
    auto stA = [&]() {
        #pragma unroll
        for (int i = 0; i < 4; i++) {
            int idx = tid + i * 256;
            int r = idx >> 3, c4 = idx & 7;
            float4 v;
            v.x = to_tf32(av[i].x); v.y = to_tf32(av[i].y);
            v.z = to_tf32(av[i].z); v.w = to_tf32(av[i].w);
            *(float4*)(As + r * 36 + c4 * 4) = v;
        }
    };
    auto cpB = [&](int kb, int buf) {
        uint32_t dst = bs_sm + buf * (4096 * NS) * 4;
        const float* s0 = W0 + (size_t)kb * 4096;
        #pragma unroll
        for (int j = 0; j < 4; j++)
            cp16(dst + (tid + j * 256) * 16, s0 + (tid + j * 256) * 4);
        if constexpr (NS == 2) {
            const float* s1 = W1 + (size_t)kb * 4096;
            #pragma unroll
            for (int j = 0; j < 4; j++)
                cp16(dst + 16384 + (tid + j * 256) * 16, s1 + (tid + j * 256) * 4);
        }
        CP_COMMIT();
    };

    ldA_regs(0);
    cpB(0, 0);
    for (int kb = 0; kb < Kb; kb++) {
        int cur = kb & 1;
        stA();
        if (kb + 1 < Kb) {
            cpB(kb + 1, cur ^ 1);
            ldA_regs(kb + 1);
            CP_WAIT1();
        } else {
            CP_WAIT0();
        }
        __syncthreads();
        const float* Bb = Bs + cur * (4096 * NS);
        #pragma unroll
        for (int ks = 0; ks < 4; ks++) {
            const float* ap = As + (w * 16 + (lane >> 2)) * 36 + ks * 8 + (lane & 3);
            uint32_t a0 = __float_as_uint(ap[0]);
            uint32_t a1 = __float_as_uint(ap[8 * 36]);
            uint32_t a2 = __float_as_uint(ap[4]);
            uint32_t a3 = __float_as_uint(ap[8 * 36 + 4]);
            #pragma unroll
            for (int nf = 0; nf < 16; nf++) {
                float2 b0 = *(const float2*)(Bb + ((nf * 4 + ks) * 32 + lane) * 2);
                mma_tf32(acc[0][nf], a0, a1, a2, a3,
                         __float_as_uint(b0.x), __float_as_uint(b0.y));
                if constexpr (NS == 2) {
                    float2 b1v = *(const float2*)(Bb + 4096 + ((nf * 4 + ks) * 32 + lane) * 2);
                    mma_tf32(acc[1][nf], a0, a1, a2, a3,
                             __float_as_uint(b1v.x), __float_as_uint(b1v.y));
                }
            }
        }
        __syncthreads();
    }

    int r0 = w * 16 + (lane >> 2);
    int row0 = m0 + r0, row1 = row0 + 8;
    #pragma unroll
    for (int s = 0; s < NS; s++) {
        #pragma unroll
        for (int nf = 0; nf < 16; nf++) {
            int lc = nf * 8 + (lane & 3) * 2;
            int col = s * 128 + lc;
            float v0 = acc[s][nf][0] + s_bias[col];
            float v1 = acc[s][nf][1] + s_bias[col + 1];
            float v2 = acc[s][nf][2] + s_bias[col];
            float v3 = acc[s][nf][3] + s_bias[col + 1];
            if (SILU) { v0 = silu_f(v0); v1 = silu_f(v1); v2 = silu_f(v2); v3 = silu_f(v3); }
            if (row0 < M) {
                if (RES) {
                    float2 r = *(const float2*)(Rsrc + (size_t)row0 * 128 + col);
                    v0 += r.x; v1 += r.y;
                }
                *(float2*)(C + (size_t)row0 * ldC + col) = make_float2(v0, v1);
                if (DUAL) *(float2*)(C2 + (size_t)row0 * ldC2 + col) = make_float2(v0, v1);
            }
            if (row1 < M) {
                if (RES) {
                    float2 r = *(const float2*)(Rsrc + (size_t)row1 * 128 + col);
                    v2 += r.x; v3 += r.y;
                }
                *(float2*)(C + (size_t)row1 * ldC + col) = make_float2(v2, v3);
                if (DUAL) *(float2*)(C2 + (size_t)row1 * ldC2 + col) = make_float2(v2, v3);
            }
        }
    }
}
#define NODE_SMEM1 51712
#define NODE_SMEM2 84992

// ================= pipelined fused edge kernel =================
// smem floats: As[16896] | Bs[8192] | src[128]i | dst[128]i | ds | wc | eb2 | cb1 | cw2
#define EDGE_SMEM 103936
__device__ __forceinline__ void edge_mma_block(const float* __restrict__ As,
                                               const float* __restrict__ Bb,
                                               float acc[16][4], int kb, int w, int lane) {
    #pragma unroll
    for (int ks = 0; ks < 4; ks++) {
        const float* ap = As + (w * 16 + (lane >> 2)) * 132 + kb * 32 + ks * 8 + (lane & 3);
        uint32_t a0 = __float_as_uint(ap[0]);
        uint32_t a1 = __float_as_uint(ap[8 * 132]);
        uint32_t a2 = __float_as_uint(ap[4]);
        uint32_t a3 = __float_as_uint(ap[8 * 132 + 4]);
        #pragma unroll
        for (int nf = 0; nf < 16; nf++) {
            float2 b = *(const float2*)(Bb + ((nf * 4 + ks) * 32 + lane) * 2);
            mma_tf32(acc[nf], a0, a1, a2, a3,
                     __float_as_uint(b.x), __float_as_uint(b.y));
        }
    }
}

__global__ void __launch_bounds__(256, 2) mma_edge(
    const int* __restrict__ esrc, const int* __restrict__ edst,
    const float* __restrict__ coords, const float* __restrict__ P,
    const float* __restrict__ wc, const float* __restrict__ eb2,
    const float* __restrict__ w2pk, const float* __restrict__ c1pk,
    const float* __restrict__ cb1, const float* __restrict__ cw2) {
    extern __shared__ float sm[];
    float* As   = sm;                    // 16896
    float* Bs   = sm + 16896;            // 8192 (2 x 4096)
    int* s_src  = (int*)(sm + 25088);
    int* s_dst  = (int*)(sm + 25216);
    float* s_ds = sm + 25344;
    float* s_wc = sm + 25472;
    float* s_eb2= sm + 25600;
    float* s_cb1= sm + 25728;
    float* s_cw2= sm + 25856;
    int tid = threadIdx.x, w = tid >> 5, lane = tid & 31;
    uint32_t bs_sm = (uint32_t)__cvta_generic_to_shared(Bs);

    auto cpB = [&](const float* src, int buf) {
        uint32_t dst = bs_sm + buf * 4096 * 4;
        #pragma unroll
        for (int j = 0; j < 4; j++)
            cp16(dst + (tid + j * 256) * 16, src + (tid + j * 256) * 4);
        CP_COMMIT();
    };

    cpB(w2pk, 0);   // prefetch GEMM1 kb0 during A build

    if (tid < 128) {
        int e = blockIdx.x * 128 + tid;
        int s = esrc[e], d = edst[e];
        s_src[tid] = s; s_dst[tid] = d;
        float dx = coords[s * 3 + 0] - coords[d * 3 + 0];
        float dy = coords[s * 3 + 1] - coords[d * 3 + 1];
        float dz = coords[s * 3 + 2] - coords[d * 3 + 2];
        s_ds[tid] = dx * dx + dy * dy + dz * dz;
        s_wc[tid] = wc[tid];
        s_eb2[tid] = eb2[tid];
        s_cb1[tid] = cb1[tid];
        s_cw2[tid] = cw2[tid];
    }
    __syncthreads();

    // ---- build A = tf32(silu(P_src + P_dst + ds*wc)) ----
    #pragma unroll
    for (int i = 0; i < 16; i++) {
        int idx = tid + i * 256;
        int r = idx >> 5, c4 = idx & 31;
        int s = s_src[r], d = s_dst[r];
        float ds = s_ds[r];
        float4 ps = *(const float4*)(P + (size_t)s * 256 + c4 * 4);
        float4 pd = *(const float4*)(P + (size_t)d * 256 + 128 + c4 * 4);
        float4 wv = *(const float4*)(s_wc + c4 * 4);
        float4 v;
        v.x = to_tf32(silu_f(ps.x + pd.x + ds * wv.x));
        v.y = to_tf32(silu_f(ps.y + pd.y + ds * wv.y));
        v.z = to_tf32(silu_f(ps.z + pd.z + ds * wv.z));
        v.w = to_tf32(silu_f(ps.w + pd.w + ds * wv.w));
        *(float4*)(As + r * 132 + c4 * 4) = v;
    }
    __syncthreads();

    float acc[16][4];
    #pragma unroll
    for (int nf = 0; nf < 16; nf++)
        #pragma unroll
        for (int j = 0; j < 4; j++) acc[nf][j] = 0.f;

    // ---- GEMM 1: pre @ eW2 (prefetch next kb; kb3 prefetches c1pk kb0) ----
    #pragma unroll
    for (int kb = 0; kb < 4; kb++) {
        const float* nxt = (kb < 3) ? (w2pk + (size_t)(kb + 1) * 4096) : c1pk;
        cpB(nxt, (kb + 1) & 1);
        CP_WAIT1();
        __syncthreads();
        edge_mma_block(As, Bs + (kb & 1) * 4096, acc, kb, w, lane);
        __syncthreads();
    }

    // ---- epilogue 1: m = silu(.+eb2) -> g_M + As (tf32) ----
    int r0 = w * 16 + (lane >> 2);
    int e0 = blockIdx.x * 128 + r0;
    #pragma unroll
    for (int nf = 0; nf < 16; nf++) {
        int col = nf * 8 + (lane & 3) * 2;
        float m0 = silu_f(acc[nf][0] + s_eb2[col]);
        float m1 = silu_f(acc[nf][1] + s_eb2[col + 1]);
        float m2 = silu_f(acc[nf][2] + s_eb2[col]);
        float m3 = silu_f(acc[nf][3] + s_eb2[col + 1]);
        *(float2*)(g_M + (size_t)e0 * 128 + col)       = make_float2(m0, m1);
        *(float2*)(g_M + (size_t)(e0 + 8) * 128 + col) = make_float2(m2, m3);
        *(float2*)(As + r0 * 132 + col)       = make_float2(to_tf32(m0), to_tf32(m1));
        *(float2*)(As + (r0 + 8) * 132 + col) = make_float2(to_tf32(m2), to_tf32(m3));
        acc[nf][0] = 0.f; acc[nf][1] = 0.f; acc[nf][2] = 0.f; acc[nf][3] = 0.f;
    }
    __syncthreads();

    // ---- GEMM 2: m @ cW1 (buffers continue: kb0 already in buf0) ----
    #pragma unroll
    for (int kb = 0; kb < 4; kb++) {
        if (kb < 3) {
            cpB(c1pk + (size_t)(kb + 1) * 4096, (kb + 1) & 1);
            CP_WAIT1();
        } else {
            CP_WAIT0();
        }
        __syncthreads();
        edge_mma_block(As, Bs + (kb & 1) * 4096, acc, kb, w, lane);
        __syncthreads();
    }

    // ---- epilogue 2: gate = silu(.+cb1) . cw2 ----
    float g0 = 0.f, g1 = 0.f;
    #pragma unroll
    for (int nf = 0; nf < 16; nf++) {
        int col = nf * 8 + (lane & 3) * 2;
        g0 += silu_f(acc[nf][0] + s_cb1[col]) * s_cw2[col]
            + silu_f(acc[nf][1] + s_cb1[col + 1]) * s_cw2[col + 1];
        g1 += silu_f(acc[nf][2] + s_cb1[col]) * s_cw2[col]
            + silu_f(acc[nf][3] + s_cb1[col + 1]) * s_cw2[col + 1];
    }
    g0 += __shfl_xor_sync(0xffffffffu, g0, 1);
    g0 += __shfl_xor_sync(0xffffffffu, g0, 2);
    g1 += __shfl_xor_sync(0xffffffffu, g1, 1);
    g1 += __shfl_xor_sync(0xffffffffu, g1, 2);
    if ((lane & 3) == 0) {
        g_gate[e0] = g0;
        g_gate[e0 + 8] = g1;
    }
}

// ================= aggregation / finalize =================
__global__ void aggregate_kernel(const int* __restrict__ esrc, const int* __restrict__ edst,
                                 const float* __restrict__ coords) {
    int n = blockIdx.x, tid = threadIdx.x;   // 128
    const float* Mrow = g_M + (size_t)n * KNB * 128;
    float mi = 0.f;
    #pragma unroll
    for (int e = 0; e < KNB; e++) mi += Mrow[e * 128 + tid];
    g_Y[n * 384 + 128 + tid] = mi;
    g_Y[n * 384 + tid] = g_h[n * 128 + tid];
    if (tid < 32) {
        float sx = 0.f, sy = 0.f, sz = 0.f;
        if (tid < KNB) {
            int e = n * KNB + tid;
            int s = esrc[e], d = edst[e];
            float dx = coords[s * 3 + 0] - coords[d * 3 + 0];
            float dy = coords[s * 3 + 1] - coords[d * 3 + 1];
            float dz = coords[s * 3 + 2] - coords[d * 3 + 2];
            float dd = dx * dx + dy * dy + dz * dz;
            float gt = g_gate[e] / sqrtf(dd + 1e-8f);
            sx = dx * gt; sy = dy * gt; sz = dz * gt;
        }
        #pragma unroll
        for (int off = 16; off; off >>= 1) {
            sx += __shfl_xor_sync(0xffffffffu, sx, off);
            sy += __shfl_xor_sync(0xffffffffu, sy, off);
            sz += __shfl_xor_sync(0xffffffffu, sz, off);
        }
        if (tid == 0) {
            g_shift[n * 3 + 0] += sx;
            g_shift[n * 3 + 1] += sy;
            g_shift[n * 3 + 2] += sz;
        }
    }
}

__global__ void finalize_kernel(float* __restrict__ out) {
    int n = blockIdx.x, tid = threadIdx.x;
    out[NN * 3 + n * 128 + tid] = g_h[n * 128 + tid];
    if (tid < 3) out[n * 3 + tid] = g_shift[n * 3 + tid];
}

// ================= host =================
extern "C" void kernel_launch(void* const* d_in, const int* in_sizes, int n_in,
                              void* d_out, int out_size) {
    const float* z      = (const float*)d_in[0];
    const float* t      = (const float*)d_in[1];
    const float* coords = (const float*)d_in[2];
    const int*   species= (const int*)d_in[3];
    const int*   batch  = (const int*)d_in[4];
    const int*   esrc   = (const int*)d_in[5];
    const int*   edst   = (const int*)d_in[6];
    const float* spemb  = (const float*)d_in[7];
    const float* tmW1   = (const float*)d_in[8];
    const float* tmb1   = (const float*)d_in[9];
    const float* tmW2   = (const float*)d_in[10];
    const float* tmb2   = (const float*)d_in[11];
    const float* neW    = (const float*)d_in[12];
    const float* neb    = (const float*)d_in[13];
    const float* eW1    = (const float*)d_in[14];
    const float* eb1    = (const float*)d_in[15];
    const float* eW2    = (const float*)d_in[16];
    const float* eb2    = (const float*)d_in[17];
    const float* cW1    = (const float*)d_in[18];
    const float* cb1    = (const float*)d_in[19];
    const float* cW2    = (const float*)d_in[20];
    const float* nW1    = (const float*)d_in[21];
    const float* nb1    = (const float*)d_in[22];
    const float* nW2    = (const float*)d_in[23];
    const float* nb2    = (const float*)d_in[24];

    float *pX0, *pX, *pY, *pP, *pU, *pH, *pPk, *pBiasP;
    cudaGetSymbolAddress((void**)&pX0,   g_X0);
    cudaGetSymbolAddress((void**)&pX,    g_X);
    cudaGetSymbolAddress((void**)&pY,    g_Y);
    cudaGetSymbolAddress((void**)&pP,    g_P);
    cudaGetSymbolAddress((void**)&pU,    g_u);
    cudaGetSymbolAddress((void**)&pH,    g_h);
    cudaGetSymbolAddress((void**)&pPk,   g_packW);
    cudaGetSymbolAddress((void**)&pBiasP, g_biasP);

    cudaFuncSetAttribute(mma_edge, cudaFuncAttributeMaxDynamicSharedMemorySize, EDGE_SMEM);
    cudaFuncSetAttribute(mma_node<1,false,false,true>,  cudaFuncAttributeMaxDynamicSharedMemorySize, NODE_SMEM1);
    cudaFuncSetAttribute(mma_node<2,false,false,false>, cudaFuncAttributeMaxDynamicSharedMemorySize, NODE_SMEM2);
    cudaFuncSetAttribute(mma_node<1,true,false,false>,  cudaFuncAttributeMaxDynamicSharedMemorySize, NODE_SMEM1);
    cudaFuncSetAttribute(mma_node<1,false,true,true>,   cudaFuncAttributeMaxDynamicSharedMemorySize, NODE_SMEM1);

    const int MT = (NN + 127) / 128;   // 157

    temb_kernel<<<NG, 128>>>(t, tmW1, tmb1, tmW2, tmb2);
    prep_kernel<<<NN, 128>>>(z, species, batch, spemb);
    build_wp4_kernel<<<dim3(256, NL), 256>>>(eW1, eb1);
    pack_kernel<<<dim3(1024, 6), 256>>>(eW2, cW1, nW2, nW1, neW);

    // h0 = [z|sp] @ neW + neb  (dual-store h, X[:, :128])
    mma_node<1, false, false, true><<<MT, 256, NODE_SMEM1>>>(
        pX0, 160, pPk + PK_NE, nullptr, neb, pH, 128, pX, 256, NN, 5, nullptr);

    for (int l = 0; l < NL; l++) {
        // P = [h|t] @ Wp  (both 128-col slabs in one pass)
        mma_node<2, false, false, false><<<MT, 256, NODE_SMEM2>>>(
            pX, 256, pPk + PK_WP + (l * 2 + 0) * 32768, pPk + PK_WP + (l * 2 + 1) * 32768,
            pBiasP + l * 256, pP, 256, nullptr, 0, NN, 8, nullptr);
        // fused edge: m + gate
        mma_edge<<<NE / 128, 256, EDGE_SMEM>>>(
            esrc, edst, coords, pP,
            eW1 + (size_t)l * 385 * 128 + 256 * 128, eb2 + l * 128,
            pPk + PK_EW2 + l * 16384, pPk + PK_CW1 + l * 16384,
            cb1 + l * 128, cW2 + l * 128);
        aggregate_kernel<<<NN, 128>>>(esrc, edst, coords);
        // u = silu([h|m_i|t] @ nW1 + nb1)
        mma_node<1, true, false, false><<<MT, 256, NODE_SMEM1>>>(
            pY, 384, pPk + PK_NW1 + l * 49152, nullptr, nb1 + l * 128,
            pU, 128, nullptr, 0, NN, 12, nullptr);
        // h = h + u @ nW2 + nb2  (dual-store h, X[:, :128])
        mma_node<1, false, true, true><<<MT, 256, NODE_SMEM1>>>(
            pU, 128, pPk + PK_NW2 + l * 16384, nullptr, nb2 + l * 128,
            pH, 128, pX, 256, NN, 4, pH);
    }

    finalize_kernel<<<NN, 128>>>((float*)d_out);
}

// round 5
// speedup vs baseline: 2.0970x; 1.1080x over previous
#include <cuda_runtime.h>
#include <math.h>
#include <stdint.h>

#define NN 20000
#define NG 400
#define KNB 12
#define NE 240000
#define NL 4

// ---- packed weight region offsets (floats) ----
#define PK_EW2 0
#define PK_CW1 65536
#define PK_NW2 131072
#define PK_NW1 196608
#define PK_NE  393216
#define PK_WP  413696
#define PK_TOTAL 675840

// ---- static device scratch ----
__device__ float g_temb[NG * 128];
__device__ float g_h[NN * 128];
__device__ float g_X[NN * 256];      // [h | t]
__device__ float g_P[NN * 256];
__device__ float g_M[NE * 128];
__device__ float g_gate[NE];
__device__ float g_u[NN * 128];
__device__ float g_packW[PK_TOTAL];
__device__ float g_biasP[NL * 256];
__device__ float g_shift[NN * 3];

__device__ __forceinline__ float silu_f(float x) {
    return __fdividef(x, 1.0f + __expf(-x));
}
__device__ __forceinline__ float to_tf32(float x) {
    float r; asm("cvt.rna.tf32.f32 %0, %1;" : "=f"(r) : "f"(x)); return r;
}

__device__ __forceinline__ void mma_tf32(float c[4], uint32_t a0, uint32_t a1,
                                         uint32_t a2, uint32_t a3,
                                         uint32_t b0, uint32_t b1) {
    asm volatile(
        "mma.sync.aligned.m16n8k8.row.col.f32.tf32.tf32.f32 "
        "{%0,%1,%2,%3}, {%4,%5,%6,%7}, {%8,%9}, {%0,%1,%2,%3};"
        : "+f"(c[0]), "+f"(c[1]), "+f"(c[2]), "+f"(c[3])
        : "r"(a0), "r"(a1), "r"(a2), "r"(a3), "r"(b0), "r"(b1));
}

__device__ __forceinline__ void cp16(uint32_t saddr, const void* g) {
    asm volatile("cp.async.ca.shared.global [%0], [%1], 16;" :: "r"(saddr), "l"(g));
}
#define CP_COMMIT() asm volatile("cp.async.commit_group;" ::: "memory")
#define CP_WAIT1()  asm volatile("cp.async.wait_group 1;" ::: "memory")
#define CP_WAIT0()  asm volatile("cp.async.wait_group 0;" ::: "memory")

// ================= launch 0: setup = pack (y<6) + temb (y==6) =================
__global__ void setup_kernel(const float* __restrict__ eW2, const float* __restrict__ cW1,
                             const float* __restrict__ nW2, const float* __restrict__ nW1,
                             const float* __restrict__ neW, const float* __restrict__ eW1,
                             const float* __restrict__ eb1,
                             const float* __restrict__ t,
                             const float* __restrict__ tmW1, const float* __restrict__ tmb1,
                             const float* __restrict__ tmW2, const float* __restrict__ tmb2) {
    int f = blockIdx.y;
    int tid = threadIdx.x;

    if (f == 6) {                       // ---- time-embedding MLP ----
        int g = blockIdx.x;
        if (g >= NG) return;
        __shared__ float e[128];
        __shared__ float hid[256];
        float tv = t[g];
        if (tid < 64) {
            float fr = expf(-(float)tid * (logf(10000.0f) / 63.0f));
            float a = tv * fr;
            e[tid] = sinf(a); e[tid + 64] = cosf(a);
        }
        __syncthreads();
        {
            float s = tmb1[tid];
            #pragma unroll 4
            for (int k = 0; k < 128; k++) s = fmaf(e[k], tmW1[k * 256 + tid], s);
            hid[tid] = silu_f(s);
        }
        __syncthreads();
        if (tid < 128) {
            float s = tmb2[tid];
            #pragma unroll 4
            for (int k = 0; k < 256; k++) s = fmaf(hid[k], tmW2[k * 128 + tid], s);
            g_temb[g * 128 + tid] = s;
        }
        return;
    }

    // ---- weight packing into fragment-major tf32 images ----
    // per 32-K block (4096 floats): idx = ((nf*4+ks)*32+lane)*2+pair
    //   k = kb*32+ks*8+(lane&3)+pair*4 ; n = nf*8+(lane>>2)
    int i = blockIdx.x * 256 + tid;
    int kb, rr, dstbase;
    const float* src = nullptr;
    if (f <= 2) {
        if (i >= 65536) return;
        const float* W = (f == 0) ? eW2 : ((f == 1) ? cW1 : nW2);
        int l = i >> 14, r14 = i & 16383;
        kb = r14 >> 12; rr = r14 & 4095;
        src = W + (size_t)l * 16384;
        dstbase = ((f == 0) ? PK_EW2 : ((f == 1) ? PK_CW1 : PK_NW2)) + l * 16384;
    } else if (f == 3) {
        if (i >= 196608) return;
        int l = i / 49152, r = i % 49152;
        kb = r >> 12; rr = r & 4095;
        src = nW1 + (size_t)l * 49152;
        dstbase = PK_NW1 + l * 49152;
    } else if (f == 4) {
        if (i >= 20480) {
            if (i < 21504) {            // biasP fill
                int idx2 = i - 20480;
                int l = idx2 >> 8, c = idx2 & 255;
                g_biasP[l * 256 + c] = (c < 128) ? eb1[l * 128 + c] : 0.f;
            }
            return;
        }
        kb = i >> 12; rr = i & 4095;
        src = neW;
        dstbase = PK_NE;
    } else {                            // f == 5: folded eW1 -> Wp [256,256]
        if (i >= 262144) return;
        int l = i >> 16, r = i & 65535, slab = r >> 15, r2 = r & 32767;
        kb = r2 >> 12; rr = r2 & 4095;
        int pair = rr & 1, lane = (rr >> 1) & 31, ks = (rr >> 6) & 3, nf = rr >> 8;
        int k = kb * 32 + ks * 8 + (lane & 3) + pair * 4;
        int n = nf * 8 + (lane >> 2);
        const float* W = eW1 + (size_t)l * 385 * 128;
        float v;
        if (slab == 0) v = (k < 128) ? W[k * 128 + n] : W[(257 + (k - 128)) * 128 + n];
        else           v = (k < 128) ? W[(128 + k) * 128 + n] : 0.f;
        g_packW[PK_WP + (l * 2 + slab) * 32768 + kb * 4096 + rr] = to_tf32(v);
        return;
    }
    int pair = rr & 1, lane = (rr >> 1) & 31, ks = (rr >> 6) & 3, nf = rr >> 8;
    int k = kb * 32 + ks * 8 + (lane & 3) + pair * 4;
    int n = nf * 8 + (lane >> 2);
    g_packW[dstbase + kb * 4096 + rr] = to_tf32(src[(size_t)k * 128 + n]);
}

// ================= pipelined node GEMM =================
// MODE 0: plain A[M,ldA]; MODE 1: NE (A=[z|spemb], + t-fill/shift-zero prologue)
// MODE 2: MI (A=[h | sum12 g_M | t])
template <int NS, int MODE, bool SILU, bool RES, bool DUAL>
__global__ void __launch_bounds__(256) mma_node(
    const float* __restrict__ A0, const float* __restrict__ A1,
    const float* __restrict__ A2, const int* __restrict__ idxp,
    const int* __restrict__ batch, int ldA,
    const float* __restrict__ W0, const float* __restrict__ W1,
    const float* __restrict__ bias,
    float* __restrict__ C, int ldC, float* __restrict__ C2, int ldC2,
    int M, int Kb, const float* __restrict__ Rsrc) {
    extern __shared__ float sm[];
    float* As = sm;
    float* Bs = sm + 4608;
    float* s_bias = Bs + 2 * 4096 * NS;
    int tid = threadIdx.x, w = tid >> 5, lane = tid & 31;
    for (int i = tid; i < NS * 128; i += 256) s_bias[i] = bias[i];
    int m0 = blockIdx.x * 128;
    uint32_t bs_sm = (uint32_t)__cvta_generic_to_shared(Bs);

    if (MODE == 1) {   // prologue side jobs: fill X t-part, zero shift
        for (int idx = tid; idx < 4096; idx += 256) {
            int r = idx >> 5, c4 = idx & 31;
            int row = m0 + r;
            if (row < NN) {
                float4 tv = *(const float4*)(g_temb + (size_t)batch[row] * 128 + c4 * 4);
                *(float4*)(g_X + (size_t)row * 256 + 128 + c4 * 4) = tv;
            }
        }
        if (tid < 128) {
            int row = m0 + tid;
            if (row < NN) {
                g_shift[row * 3 + 0] = 0.f;
                g_shift[row * 3 + 1] = 0.f;
                g_shift[row * 3 + 2] = 0.f;
            }
        }
    }

    float acc[NS][16][4];
    #pragma unroll
    for (int s = 0; s < NS; s++)
        #pragma unroll
        for (int nf = 0; nf < 16; nf++)
            #pragma unroll
            for (int j = 0; j < 4; j++) acc[s][nf][j] = 0.f;

    float4 av[4];
    auto ldA_regs = [&](int kb) {
        #pragma unroll
        for (int i = 0; i < 4; i++) {
            int idx = tid + i * 256;
            int r = idx >> 3, c4 = idx & 7;
            int row = m0 + r;
            float4 v = make_float4(0.f, 0.f, 0.f, 0.f);
            if (row < M) {
                if (MODE == 0) {
                    v = *(const float4*)(A0 + (size_t)row * ldA + kb * 32 + c4 * 4);
                } else if (MODE == 1) {
                    if (kb < 4) v = *(const float4*)(A0 + (size_t)row * 128 + kb * 32 + c4 * 4);
                    else        v = *(const float4*)(A1 + (size_t)idxp[row] * 32 + c4 * 4);
                } else {
                    if (kb < 4) {
                        v = *(const float4*)(A0 + (size_t)row * 128 + kb * 32 + c4 * 4);
                    } else if (kb < 8) {
                        const float* base = A1 + (size_t)row * KNB * 128 + (kb - 4) * 32 + c4 * 4;
                        #pragma unroll
                        for (int j = 0; j < KNB; j++) {
                            float4 mv = *(const float4*)(base + j * 128);
                            v.x += mv.x; v.y += mv.y; v.z += mv.z; v.w += mv.w;
                        }
                    } else {
                        v = *(const float4*)(A2 + (size_t)row * 256 + (kb - 8) * 32 + c4 * 4);
                    }
                }
            }
            av[i] = v;
        }
    };
    auto stA = [&]() {
        #pragma unroll
        for (int i = 0; i < 4; i++) {
            int idx = tid + i * 256;
            int r = idx >> 3, c4 = idx & 7;
            float4 v;
            v.x = to_tf32(av[i].x); v.y = to_tf32(av[i].y);
            v.z = to_tf32(av[i].z); v.w = to_tf32(av[i].w);
            *(float4*)(As + r * 36 + c4 * 4) = v;
        }
    };
    auto cpB = [&](int kb, int buf) {
        uint32_t dst = bs_sm + buf * (4096 * NS) * 4;
        const float* s0 = W0 + (size_t)kb * 4096;
        #pragma unroll
        for (int j = 0; j < 4; j++)
            cp16(dst + (tid + j * 256) * 16, s0 + (tid + j * 256) * 4);
        if constexpr (NS == 2) {
            const float* s1 = W1 + (size_t)kb * 4096;
            #pragma unroll
            for (int j = 0; j < 4; j++)
                cp16(dst + 16384 + (tid + j * 256) * 16, s1 + (tid + j * 256) * 4);
        }
        CP_COMMIT();
    };

    ldA_regs(0);
    cpB(0, 0);
    for (int kb = 0; kb < Kb; kb++) {
        int cur = kb & 1;
        stA();
        if (kb + 1 < Kb) {
            cpB(kb + 1, cur ^ 1);
            ldA_regs(kb + 1);
            CP_WAIT1();
        } else {
            CP_WAIT0();
        }
        __syncthreads();
        const float* Bb = Bs + cur * (4096 * NS);
        #pragma unroll
        for (int ks = 0; ks < 4; ks++) {
            const float* ap = As + (w * 16 + (lane >> 2)) * 36 + ks * 8 + (lane & 3);
            uint32_t a0 = __float_as_uint(ap[0]);
            uint32_t a1 = __float_as_uint(ap[8 * 36]);
            uint32_t a2 = __float_as_uint(ap[4]);
            uint32_t a3 = __float_as_uint(ap[8 * 36 + 4]);
            #pragma unroll
            for (int nf = 0; nf < 16; nf++) {
                float2 b0 = *(const float2*)(Bb + ((nf * 4 + ks) * 32 + lane) * 2);
                mma_tf32(acc[0][nf], a0, a1, a2, a3,
                         __float_as_uint(b0.x), __float_as_uint(b0.y));
                if constexpr (NS == 2) {
                    float2 b1v = *(const float2*)(Bb + 4096 + ((nf * 4 + ks) * 32 + lane) * 2);
                    mma_tf32(acc[1][nf], a0, a1, a2, a3,
                             __float_as_uint(b1v.x), __float_as_uint(b1v.y));
                }
            }
        }
        __syncthreads();
    }

    int r0 = w * 16 + (lane >> 2);
    int row0 = m0 + r0, row1 = row0 + 8;
    #pragma unroll
    for (int s = 0; s < NS; s++) {
        #pragma unroll
        for (int nf = 0; nf < 16; nf++) {
            int lc = nf * 8 + (lane & 3) * 2;
            int col = s * 128 + lc;
            float v0 = acc[s][nf][0] + s_bias[col];
            float v1 = acc[s][nf][1] + s_bias[col + 1];
            float v2 = acc[s][nf][2] + s_bias[col];
            float v3 = acc[s][nf][3] + s_bias[col + 1];
            if (SILU) { v0 = silu_f(v0); v1 = silu_f(v1); v2 = silu_f(v2); v3 = silu_f(v3); }
            if (row0 < M) {
                if (RES) {
                    float2 r = *(const float2*)(Rsrc + (size_t)row0 * 128 + col);
                    v0 += r.x; v1 += r.y;
                }
                *(float2*)(C + (size_t)row0 * ldC + col) = make_float2(v0, v1);
                if (DUAL) *(float2*)(C2 + (size_t)row0 * ldC2 + col) = make_float2(v0, v1);
            }
            if (row1 < M) {
                if (RES) {
                    float2 r = *(const float2*)(Rsrc + (size_t)row1 * 128 + col);
                    v2 += r.x; v3 += r.y;
                }
                *(float2*)(C + (size_t)row1 * ldC + col) = make_float2(v2, v3);
                if (DUAL) *(float2*)(C2 + (size_t)row1 * ldC2 + col) = make_float2(v2, v3);
            }
        }
    }
}
#define NODE_SMEM1 51712
#define NODE_SMEM2 84992

// ================= fused edge kernel: 128 thr, 4 warps, M=32/warp =================
#define EDGE_SMEM 103936
__global__ void __launch_bounds__(128) mma_edge(
    const int* __restrict__ esrc, const int* __restrict__ edst,
    const float* __restrict__ coords, const float* __restrict__ P,
    const float* __restrict__ wc, const float* __restrict__ eb2,
    const float* __restrict__ w2pk, const float* __restrict__ c1pk,
    const float* __restrict__ cb1, const float* __restrict__ cw2) {
    extern __shared__ float sm[];
    float* As   = sm;                    // 128 x 132 = 16896
    float* Bs   = sm + 16896;            // 2 x 4096
    int* s_src  = (int*)(sm + 25088);
    int* s_dst  = (int*)(sm + 25216);
    float* s_ds = sm + 25344;
    float* s_wc = sm + 25472;
    float* s_eb2= sm + 25600;
    float* s_cb1= sm + 25728;
    float* s_cw2= sm + 25856;
    int tid = threadIdx.x, w = tid >> 5, lane = tid & 31;
    uint32_t bs_sm = (uint32_t)__cvta_generic_to_shared(Bs);

    auto cpB = [&](const float* src, int buf) {
        uint32_t dst = bs_sm + buf * 4096 * 4;
        #pragma unroll
        for (int j = 0; j < 8; j++)
            cp16(dst + (tid + j * 128) * 16, src + (tid + j * 128) * 4);
        CP_COMMIT();
    };

    cpB(w2pk, 0);   // prefetch GEMM1 kb0 during edge-meta + A build

    {
        int e = blockIdx.x * 128 + tid;
        int s = esrc[e], d = edst[e];
        s_src[tid] = s; s_dst[tid] = d;
        float dx = coords[s * 3 + 0] - coords[d * 3 + 0];
        float dy = coords[s * 3 + 1] - coords[d * 3 + 1];
        float dz = coords[s * 3 + 2] - coords[d * 3 + 2];
        s_ds[tid] = dx * dx + dy * dy + dz * dz;
        s_wc[tid] = wc[tid];
        s_eb2[tid] = eb2[tid];
        s_cb1[tid] = cb1[tid];
        s_cw2[tid] = cw2[tid];
    }
    __syncthreads();

    // ---- build A = tf32(silu(P_src + P_dst + ds*wc)) ----
    #pragma unroll
    for (int i = 0; i < 32; i++) {
        int idx = tid + i * 128;
        int r = idx >> 5, c4 = idx & 31;
        int s = s_src[r], d = s_dst[r];
        float ds = s_ds[r];
        float4 ps = *(const float4*)(P + (size_t)s * 256 + c4 * 4);
        float4 pd = *(const float4*)(P + (size_t)d * 256 + 128 + c4 * 4);
        float4 wv = *(const float4*)(s_wc + c4 * 4);
        float4 v;
        v.x = to_tf32(silu_f(ps.x + pd.x + ds * wv.x));
        v.y = to_tf32(silu_f(ps.y + pd.y + ds * wv.y));
        v.z = to_tf32(silu_f(ps.z + pd.z + ds * wv.z));
        v.w = to_tf32(silu_f(ps.w + pd.w + ds * wv.w));
        *(float4*)(As + r * 132 + c4 * 4) = v;
    }
    __syncthreads();

    float acc[2][16][4];
    #pragma unroll
    for (int fb = 0; fb < 2; fb++)
        #pragma unroll
        for (int nf = 0; nf < 16; nf++)
            #pragma unroll
            for (int j = 0; j < 4; j++) acc[fb][nf][j] = 0.f;

    int rA = w * 32 + (lane >> 2);

    auto gemm_block = [&](const float* Bb, int kb) {
        #pragma unroll
        for (int ks = 0; ks < 4; ks++) {
            const float* ap = As + rA * 132 + kb * 32 + ks * 8 + (lane & 3);
            uint32_t a00 = __float_as_uint(ap[0]);
            uint32_t a01 = __float_as_uint(ap[8 * 132]);
            uint32_t a02 = __float_as_uint(ap[4]);
            uint32_t a03 = __float_as_uint(ap[8 * 132 + 4]);
            uint32_t a10 = __float_as_uint(ap[16 * 132]);
            uint32_t a11 = __float_as_uint(ap[24 * 132]);
            uint32_t a12 = __float_as_uint(ap[16 * 132 + 4]);
            uint32_t a13 = __float_as_uint(ap[24 * 132 + 4]);
            #pragma unroll
            for (int nf = 0; nf < 16; nf++) {
                float2 b = *(const float2*)(Bb + ((nf * 4 + ks) * 32 + lane) * 2);
                uint32_t b0 = __float_as_uint(b.x), b1 = __float_as_uint(b.y);
                mma_tf32(acc[0][nf], a00, a01, a02, a03, b0, b1);
                mma_tf32(acc[1][nf], a10, a11, a12, a13, b0, b1);
            }
        }
    };

    // ---- GEMM 1: pre @ eW2 ----
    #pragma unroll
    for (int kb = 0; kb < 4; kb++) {
        const float* nxt = (kb < 3) ? (w2pk + (size_t)(kb + 1) * 4096) : c1pk;
        cpB(nxt, (kb + 1) & 1);
        CP_WAIT1();
        __syncthreads();
        gemm_block(Bs + (kb & 1) * 4096, kb);
        __syncthreads();
    }

    // ---- epilogue 1: m = silu(.+eb2) -> g_M + As (tf32) ----
    int r0 = w * 32 + (lane >> 2);
    int e0 = blockIdx.x * 128 + r0;
    #pragma unroll
    for (int fb = 0; fb < 2; fb++) {
        int ra = r0 + fb * 16, ea = e0 + fb * 16;
        #pragma unroll
        for (int nf = 0; nf < 16; nf++) {
            int col = nf * 8 + (lane & 3) * 2;
            float m0 = silu_f(acc[fb][nf][0] + s_eb2[col]);
            float m1 = silu_f(acc[fb][nf][1] + s_eb2[col + 1]);
            float m2 = silu_f(acc[fb][nf][2] + s_eb2[col]);
            float m3 = silu_f(acc[fb][nf][3] + s_eb2[col + 1]);
            *(float2*)(g_M + (size_t)ea * 128 + col)       = make_float2(m0, m1);
            *(float2*)(g_M + (size_t)(ea + 8) * 128 + col) = make_float2(m2, m3);
            *(float2*)(As + ra * 132 + col)       = make_float2(to_tf32(m0), to_tf32(m1));
            *(float2*)(As + (ra + 8) * 132 + col) = make_float2(to_tf32(m2), to_tf32(m3));
            acc[fb][nf][0] = 0.f; acc[fb][nf][1] = 0.f;
            acc[fb][nf][2] = 0.f; acc[fb][nf][3] = 0.f;
        }
    }
    __syncthreads();

    // ---- GEMM 2: m @ cW1 ----
    #pragma unroll
    for (int kb = 0; kb < 4; kb++) {
        if (kb < 3) {
            cpB(c1pk + (size_t)(kb + 1) * 4096, (kb + 1) & 1);
            CP_WAIT1();
        } else {
            CP_WAIT0();
        }
        __syncthreads();
        gemm_block(Bs + (kb & 1) * 4096, kb);
        __syncthreads();
    }

    // ---- epilogue 2: gate = silu(.+cb1) . cw2 ----
    #pragma unroll
    for (int fb = 0; fb < 2; fb++) {
        float g0 = 0.f, g1 = 0.f;
        #pragma unroll
        for (int nf = 0; nf < 16; nf++) {
            int col = nf * 8 + (lane & 3) * 2;
            g0 += silu_f(acc[fb][nf][0] + s_cb1[col]) * s_cw2[col]
                + silu_f(acc[fb][nf][1] + s_cb1[col + 1]) * s_cw2[col + 1];
            g1 += silu_f(acc[fb][nf][2] + s_cb1[col]) * s_cw2[col]
                + silu_f(acc[fb][nf][3] + s_cb1[col + 1]) * s_cw2[col + 1];
        }
        g0 += __shfl_xor_sync(0xffffffffu, g0, 1);
        g0 += __shfl_xor_sync(0xffffffffu, g0, 2);
        g1 += __shfl_xor_sync(0xffffffffu, g1, 1);
        g1 += __shfl_xor_sync(0xffffffffu, g1, 2);
        if ((lane & 3) == 0) {
            g_gate[e0 + fb * 16]     = g0;
            g_gate[e0 + fb * 16 + 8] = g1;
        }
    }
}

// ================= shift accumulation (per node, warp per node) =================
__global__ void shift_kernel(const int* __restrict__ esrc, const int* __restrict__ edst,
                             const float* __restrict__ coords) {
    int tid = threadIdx.x;                 // 128: 4 warps = 4 nodes
    int n = blockIdx.x * 4 + (tid >> 5);
    int lane = tid & 31;
    if (n >= NN) return;
    float sx = 0.f, sy = 0.f, sz = 0.f;
    if (lane < KNB) {
        int e = n * KNB + lane;
        int s = esrc[e], d = edst[e];
        float dx = coords[s * 3 + 0] - coords[d * 3 + 0];
        float dy = coords[s * 3 + 1] - coords[d * 3 + 1];
        float dz = coords[s * 3 + 2] - coords[d * 3 + 2];
        float dd = dx * dx + dy * dy + dz * dz;
        float gt = g_gate[e] * __frsqrt_rn(dd + 1e-8f);
        sx = dx * gt; sy = dy * gt; sz = dz * gt;
    }
    #pragma unroll
    for (int off = 8; off; off >>= 1) {
        sx += __shfl_down_sync(0xffffffffu, sx, off);
        sy += __shfl_down_sync(0xffffffffu, sy, off);
        sz += __shfl_down_sync(0xffffffffu, sz, off);
    }
    if (lane == 0) {
        g_shift[n * 3 + 0] += sx;
        g_shift[n * 3 + 1] += sy;
        g_shift[n * 3 + 2] += sz;
    }
}

__global__ void finalize_kernel(float* __restrict__ out) {
    int n = blockIdx.x, tid = threadIdx.x;
    out[NN * 3 + n * 128 + tid] = g_h[n * 128 + tid];
    if (tid < 3) out[n * 3 + tid] = g_shift[n * 3 + tid];
}

// ================= host =================
extern "C" void kernel_launch(void* const* d_in, const int* in_sizes, int n_in,
                              void* d_out, int out_size) {
    const float* z      = (const float*)d_in[0];
    const float* t      = (const float*)d_in[1];
    const float* coords = (const float*)d_in[2];
    const int*   species= (const int*)d_in[3];
    const int*   batch  = (const int*)d_in[4];
    const int*   esrc   = (const int*)d_in[5];
    const int*   edst   = (const int*)d_in[6];
    const float* spemb  = (const float*)d_in[7];
    const float* tmW1   = (const float*)d_in[8];
    const float* tmb1   = (const float*)d_in[9];
    const float* tmW2   = (const float*)d_in[10];
    const float* tmb2   = (const float*)d_in[11];
    const float* neW    = (const float*)d_in[12];
    const float* neb    = (const float*)d_in[13];
    const float* eW1    = (const float*)d_in[14];
    const float* eb1    = (const float*)d_in[15];
    const float* eW2    = (const float*)d_in[16];
    const float* eb2    = (const float*)d_in[17];
    const float* cW1    = (const float*)d_in[18];
    const float* cb1    = (const float*)d_in[19];
    const float* cW2    = (const float*)d_in[20];
    const float* nW1    = (const float*)d_in[21];
    const float* nb1    = (const float*)d_in[22];
    const float* nW2    = (const float*)d_in[23];
    const float* nb2    = (const float*)d_in[24];

    float *pX, *pP, *pU, *pH, *pM, *pPk, *pBiasP;
    cudaGetSymbolAddress((void**)&pX,    g_X);
    cudaGetSymbolAddress((void**)&pP,    g_P);
    cudaGetSymbolAddress((void**)&pU,    g_u);
    cudaGetSymbolAddress((void**)&pH,    g_h);
    cudaGetSymbolAddress((void**)&pM,    g_M);
    cudaGetSymbolAddress((void**)&pPk,   g_packW);
    cudaGetSymbolAddress((void**)&pBiasP, g_biasP);

    cudaFuncSetAttribute(mma_edge, cudaFuncAttributeMaxDynamicSharedMemorySize, EDGE_SMEM);
    cudaFuncSetAttribute(mma_node<1,1,false,false,true>,  cudaFuncAttributeMaxDynamicSharedMemorySize, NODE_SMEM1);
    cudaFuncSetAttribute(mma_node<2,0,false,false,false>, cudaFuncAttributeMaxDynamicSharedMemorySize, NODE_SMEM2);
    cudaFuncSetAttribute(mma_node<1,2,true,false,false>,  cudaFuncAttributeMaxDynamicSharedMemorySize, NODE_SMEM1);
    cudaFuncSetAttribute(mma_node<1,0,false,true,true>,   cudaFuncAttributeMaxDynamicSharedMemorySize, NODE_SMEM1);

    const int MT = (NN + 127) / 128;   // 157

    // launch 0: setup (pack + temb)
    setup_kernel<<<dim3(1024, 7), 256>>>(eW2, cW1, nW2, nW1, neW, eW1, eb1,
                                         t, tmW1, tmb1, tmW2, tmb2);
    // launch 1: h0 = [z|sp] @ neW + neb (dual-store h, X[:, :128]; prologue t-fill + shift zero)
    mma_node<1, 1, false, false, true><<<MT, 256, NODE_SMEM1>>>(
        z, spemb, nullptr, species, batch, 128,
        pPk + PK_NE, nullptr, neb, pH, 128, pX, 256, NN, 5, nullptr);

    for (int l = 0; l < NL; l++) {
        // P = [h|t] @ Wp  (both 128-col slabs in one pass)   [launch 2 for l=0]
        mma_node<2, 0, false, false, false><<<MT, 256, NODE_SMEM2>>>(
            pX, nullptr, nullptr, nullptr, nullptr, 256,
            pPk + PK_WP + (l * 2 + 0) * 32768, pPk + PK_WP + (l * 2 + 1) * 32768,
            pBiasP + l * 256, pP, 256, nullptr, 0, NN, 8, nullptr);
        // fused edge: m + gate   [launch 3 for l=0 -> ncu capture]
        mma_edge<<<NE / 128, 128, EDGE_SMEM>>>(
            esrc, edst, coords, pP,
            eW1 + (size_t)l * 385 * 128 + 256 * 128, eb2 + l * 128,
            pPk + PK_EW2 + l * 16384, pPk + PK_CW1 + l * 16384,
            cb1 + l * 128, cW2 + l * 128);
        // shift accumulation
        shift_kernel<<<(NN + 3) / 4, 128>>>(esrc, edst, coords);
        // u = silu([h | sum12 m | t] @ nW1 + nb1)  (MI loader, no agg pass)
        mma_node<1, 2, true, false, false><<<MT, 256, NODE_SMEM1>>>(
            pH, pM, pX + 128, nullptr, nullptr, 0,
            pPk + PK_NW1 + l * 49152, nullptr, nb1 + l * 128,
            pU, 128, nullptr, 0, NN, 12, nullptr);
        // h = h + u @ nW2 + nb2  (dual-store h, X[:, :128])
        mma_node<1, 0, false, true, true><<<MT, 256, NODE_SMEM1>>>(
            pU, nullptr, nullptr, nullptr, nullptr, 128,
            pPk + PK_NW2 + l * 16384, nullptr, nb2 + l * 128,
            pH, 128, pX, 256, NN, 4, pH);
    }

    finalize_kernel<<<NN, 128>>>((float*)d_out);
}

// round 7
// speedup vs baseline: 2.3420x; 1.1168x over previous
#include <cuda_runtime.h>
#include <math.h>
#include <stdint.h>

#define NN 20000
#define NG 400
#define KNB 12
#define NE 240000
#define NL 4

// ---- packed weight region offsets (floats) ----
#define PK_EW2 0
#define PK_CW1 65536
#define PK_NW2 131072
#define PK_NW1 196608
#define PK_NE  393216
#define PK_WP  413696
#define PK_TOTAL 675840

// ---- static device scratch ----
__device__ float g_temb[NG * 128];
__device__ float g_h[NN * 128];
__device__ float g_X[NN * 256];      // [h | t]
__device__ float g_P[NN * 256];
__device__ float g_M[NE * 128];      // tf32-rounded messages
__device__ float g_gate[NE];
__device__ float g_u[NN * 128];
__device__ float g_packW[PK_TOTAL];
__device__ float g_biasP[NL * 256];
__device__ float g_shift[NN * 3];

__device__ __forceinline__ float silu_f(float x) {
    return __fdividef(x, 1.0f + __expf(-x));
}
__device__ __forceinline__ float to_tf32(float x) {
    float r; asm("cvt.rna.tf32.f32 %0, %1;" : "=f"(r) : "f"(x)); return r;
}

__device__ __forceinline__ void mma_tf32(float c[4], uint32_t a0, uint32_t a1,
                                         uint32_t a2, uint32_t a3,
                                         uint32_t b0, uint32_t b1) {
    asm volatile(
        "mma.sync.aligned.m16n8k8.row.col.f32.tf32.tf32.f32 "
        "{%0,%1,%2,%3}, {%4,%5,%6,%7}, {%8,%9}, {%0,%1,%2,%3};"
        : "+f"(c[0]), "+f"(c[1]), "+f"(c[2]), "+f"(c[3])
        : "r"(a0), "r"(a1), "r"(a2), "r"(a3), "r"(b0), "r"(b1));
}

__device__ __forceinline__ void cp16(uint32_t saddr, const void* g) {
    asm volatile("cp.async.ca.shared.global [%0], [%1], 16;" :: "r"(saddr), "l"(g));
}
#define CP_COMMIT() asm volatile("cp.async.commit_group;" ::: "memory")
#define CP_WAIT1()  asm volatile("cp.async.wait_group 1;" ::: "memory")
#define CP_WAIT0()  asm volatile("cp.async.wait_group 0;" ::: "memory")

// ================= launch 0: setup = pack (y<6) + temb (y==6) =================
__global__ void setup_kernel(const float* __restrict__ eW2, const float* __restrict__ cW1,
                             const float* __restrict__ nW2, const float* __restrict__ nW1,
                             const float* __restrict__ neW, const float* __restrict__ eW1,
                             const float* __restrict__ eb1,
                             const float* __restrict__ t,
                             const float* __restrict__ tmW1, const float* __restrict__ tmb1,
                             const float* __restrict__ tmW2, const float* __restrict__ tmb2) {
    int f = blockIdx.y;
    int tid = threadIdx.x;

    if (f == 6) {                       // ---- time-embedding MLP ----
        int g = blockIdx.x;
        if (g >= NG) return;
        __shared__ float e[128];
        __shared__ float hid[256];
        float tv = t[g];
        if (tid < 64) {
            float fr = expf(-(float)tid * (logf(10000.0f) / 63.0f));
            float a = tv * fr;
            e[tid] = sinf(a); e[tid + 64] = cosf(a);
        }
        __syncthreads();
        {
            float s = tmb1[tid];
            #pragma unroll 4
            for (int k = 0; k < 128; k++) s = fmaf(e[k], tmW1[k * 256 + tid], s);
            hid[tid] = silu_f(s);
        }
        __syncthreads();
        if (tid < 128) {
            float s = tmb2[tid];
            #pragma unroll 4
            for (int k = 0; k < 256; k++) s = fmaf(hid[k], tmW2[k * 128 + tid], s);
            g_temb[g * 128 + tid] = s;
        }
        return;
    }

    // ---- weight packing into fragment-major tf32 images ----
    int i = blockIdx.x * 256 + tid;
    int kb, rr, dstbase;
    const float* src = nullptr;
    if (f <= 2) {
        if (i >= 65536) return;
        const float* W = (f == 0) ? eW2 : ((f == 1) ? cW1 : nW2);
        int l = i >> 14, r14 = i & 16383;
        kb = r14 >> 12; rr = r14 & 4095;
        src = W + (size_t)l * 16384;
        dstbase = ((f == 0) ? PK_EW2 : ((f == 1) ? PK_CW1 : PK_NW2)) + l * 16384;
    } else if (f == 3) {
        if (i >= 196608) return;
        int l = i / 49152, r = i % 49152;
        kb = r >> 12; rr = r & 4095;
        src = nW1 + (size_t)l * 49152;
        dstbase = PK_NW1 + l * 49152;
    } else if (f == 4) {
        if (i >= 20480) {
            if (i < 21504) {
                int idx2 = i - 20480;
                int l = idx2 >> 8, c = idx2 & 255;
                g_biasP[l * 256 + c] = (c < 128) ? eb1[l * 128 + c] : 0.f;
            }
            return;
        }
        kb = i >> 12; rr = i & 4095;
        src = neW;
        dstbase = PK_NE;
    } else {                            // f == 5: folded eW1 -> Wp
        if (i >= 262144) return;
        int l = i >> 16, r = i & 65535, slab = r >> 15, r2 = r & 32767;
        kb = r2 >> 12; rr = r2 & 4095;
        int pair = rr & 1, lane = (rr >> 1) & 31, ks = (rr >> 6) & 3, nf = rr >> 8;
        int k = kb * 32 + ks * 8 + (lane & 3) + pair * 4;
        int n = nf * 8 + (lane >> 2);
        const float* W = eW1 + (size_t)l * 385 * 128;
        float v;
        if (slab == 0) v = (k < 128) ? W[k * 128 + n] : W[(257 + (k - 128)) * 128 + n];
        else           v = (k < 128) ? W[(128 + k) * 128 + n] : 0.f;
        g_packW[PK_WP + (l * 2 + slab) * 32768 + kb * 4096 + rr] = to_tf32(v);
        return;
    }
    int pair = rr & 1, lane = (rr >> 1) & 31, ks = (rr >> 6) & 3, nf = rr >> 8;
    int k = kb * 32 + ks * 8 + (lane & 3) + pair * 4;
    int n = nf * 8 + (lane >> 2);
    g_packW[dstbase + kb * 4096 + rr] = to_tf32(src[(size_t)k * 128 + n]);
}

// ================= pipelined node GEMM =================
template <int NS, int MODE, bool SILU, bool RES, bool DUAL>
__global__ void __launch_bounds__(256) mma_node(
    const float* __restrict__ A0, const float* __restrict__ A1,
    const float* __restrict__ A2, const int* __restrict__ idxp,
    const int* __restrict__ batch, int ldA,
    const float* __restrict__ W0, const float* __restrict__ W1,
    const float* __restrict__ bias,
    float* __restrict__ C, int ldC, float* __restrict__ C2, int ldC2,
    int M, int Kb, const float* __restrict__ Rsrc) {
    extern __shared__ float sm[];
    float* As = sm;
    float* Bs = sm + 4608;
    float* s_bias = Bs + 2 * 4096 * NS;
    int tid = threadIdx.x, w = tid >> 5, lane = tid & 31;
    for (int i = tid; i < NS * 128; i += 256) s_bias[i] = bias[i];
    int m0 = blockIdx.x * 128;
    uint32_t bs_sm = (uint32_t)__cvta_generic_to_shared(Bs);

    if (MODE == 1) {
        for (int idx = tid; idx < 4096; idx += 256) {
            int r = idx >> 5, c4 = idx & 31;
            int row = m0 + r;
            if (row < NN) {
                float4 tv = *(const float4*)(g_temb + (size_t)batch[row] * 128 + c4 * 4);
                *(float4*)(g_X + (size_t)row * 256 + 128 + c4 * 4) = tv;
            }
        }
        if (tid < 128) {
            int row = m0 + tid;
            if (row < NN) {
                g_shift[row * 3 + 0] = 0.f;
                g_shift[row * 3 + 1] = 0.f;
                g_shift[row * 3 + 2] = 0.f;
            }
        }
    }

    float acc[NS][16][4];
    #pragma unroll
    for (int s = 0; s < NS; s++)
        #pragma unroll
        for (int nf = 0; nf < 16; nf++)
            #pragma unroll
            for (int j = 0; j < 4; j++) acc[s][nf][j] = 0.f;

    float4 av[4];
    auto ldA_regs = [&](int kb) {
        #pragma unroll
        for (int i = 0; i < 4; i++) {
            int idx = tid + i * 256;
            int r = idx >> 3, c4 = idx & 7;
            int row = m0 + r;
            float4 v = make_float4(0.f, 0.f, 0.f, 0.f);
            if (row < M) {
                if (MODE == 0) {
                    v = *(const float4*)(A0 + (size_t)row * ldA + kb * 32 + c4 * 4);
                } else if (MODE == 1) {
                    if (kb < 4) v = *(const float4*)(A0 + (size_t)row * 128 + kb * 32 + c4 * 4);
                    else        v = *(const float4*)(A1 + (size_t)idxp[row] * 32 + c4 * 4);
                } else {
                    if (kb < 4) {
                        v = *(const float4*)(A0 + (size_t)row * 128 + kb * 32 + c4 * 4);
                    } else if (kb < 8) {
                        const float* base = A1 + (size_t)row * KNB * 128 + (kb - 4) * 32 + c4 * 4;
                        #pragma unroll
                        for (int j = 0; j < KNB; j++) {
                            float4 mv = *(const float4*)(base + j * 128);
                            v.x += mv.x; v.y += mv.y; v.z += mv.z; v.w += mv.w;
                        }
                    } else {
                        v = *(const float4*)(A2 + (size_t)row * 256 + (kb - 8) * 32 + c4 * 4);
                    }
                }
            }
            av[i] = v;
        }
    };
    auto stA = [&]() {
        #pragma unroll
        for (int i = 0; i < 4; i++) {
            int idx = tid + i * 256;
            int r = idx >> 3, c4 = idx & 7;
            float4 v;
            v.x = to_tf32(av[i].x); v.y = to_tf32(av[i].y);
            v.z = to_tf32(av[i].z); v.w = to_tf32(av[i].w);
            *(float4*)(As + r * 36 + c4 * 4) = v;
        }
    };
    auto cpB = [&](int kb, int buf) {
        uint32_t dst = bs_sm + buf * (4096 * NS) * 4;
        const float* s0 = W0 + (size_t)kb * 4096;
        #pragma unroll
        for (int j = 0; j < 4; j++)
            cp16(dst + (tid + j * 256) * 16, s0 + (tid + j * 256) * 4);
        if constexpr (NS == 2) {
            const float* s1 = W1 + (size_t)kb * 4096;
            #pragma unroll
            for (int j = 0; j < 4; j++)
                cp16(dst + 16384 + (tid + j * 256) * 16, s1 + (tid + j * 256) * 4);
        }
        CP_COMMIT();
    };

    ldA_regs(0);
    cpB(0, 0);
    for (int kb = 0; kb < Kb; kb++) {
        int cur = kb & 1;
        stA();
        if (kb + 1 < Kb) {
            cpB(kb + 1, cur ^ 1);
            ldA_regs(kb + 1);
            CP_WAIT1();
        } else {
            CP_WAIT0();
        }
        __syncthreads();
        const float* Bb = Bs + cur * (4096 * NS);
        #pragma unroll
        for (int ks = 0; ks < 4; ks++) {
            const float* ap = As + (w * 16 + (lane >> 2)) * 36 + ks * 8 + (lane & 3);
            uint32_t a0 = __float_as_uint(ap[0]);
            uint32_t a1 = __float_as_uint(ap[8 * 36]);
            uint32_t a2 = __float_as_uint(ap[4]);
            uint32_t a3 = __float_as_uint(ap[8 * 36 + 4]);
            #pragma unroll
            for (int nf = 0; nf < 16; nf++) {
                float2 b0 = *(const float2*)(Bb + ((nf * 4 + ks) * 32 + lane) * 2);
                mma_tf32(acc[0][nf], a0, a1, a2, a3,
                         __float_as_uint(b0.x), __float_as_uint(b0.y));
                if constexpr (NS == 2) {
                    float2 b1v = *(const float2*)(Bb + 4096 + ((nf * 4 + ks) * 32 + lane) * 2);
                    mma_tf32(acc[1][nf], a0, a1, a2, a3,
                             __float_as_uint(b1v.x), __float_as_uint(b1v.y));
                }
            }
        }
        __syncthreads();
    }

    int r0 = w * 16 + (lane >> 2);
    int row0 = m0 + r0, row1 = row0 + 8;
    #pragma unroll
    for (int s = 0; s < NS; s++) {
        #pragma unroll
        for (int nf = 0; nf < 16; nf++) {
            int lc = nf * 8 + (lane & 3) * 2;
            int col = s * 128 + lc;
            float v0 = acc[s][nf][0] + s_bias[col];
            float v1 = acc[s][nf][1] + s_bias[col + 1];
            float v2 = acc[s][nf][2] + s_bias[col];
            float v3 = acc[s][nf][3] + s_bias[col + 1];
            if (SILU) { v0 = silu_f(v0); v1 = silu_f(v1); v2 = silu_f(v2); v3 = silu_f(v3); }
            if (row0 < M) {
                if (RES) {
                    float2 r = *(const float2*)(Rsrc + (size_t)row0 * 128 + col);
                    v0 += r.x; v1 += r.y;
                }
                *(float2*)(C + (size_t)row0 * ldC + col) = make_float2(v0, v1);
                if (DUAL) *(float2*)(C2 + (size_t)row0 * ldC2 + col) = make_float2(v0, v1);
            }
            if (row1 < M) {
                if (RES) {
                    float2 r = *(const float2*)(Rsrc + (size_t)row1 * 128 + col);
                    v2 += r.x; v3 += r.y;
                }
                *(float2*)(C + (size_t)row1 * ldC + col) = make_float2(v2, v3);
                if (DUAL) *(float2*)(C2 + (size_t)row1 * ldC2 + col) = make_float2(v2, v3);
            }
        }
    }
}
#define NODE_SMEM1 51712
#define NODE_SMEM2 84992

// ================= fused edge kernel: 256 thr, 8 warps, single-A двух-sync =================
// smem floats: As[4608] | Bs[2][4096] | meta 896 -> 13696 fl = 54784 B
#define EDGE_SMEM 54784
__global__ void __launch_bounds__(256, 2) mma_edge(
    const int* __restrict__ esrc, const int* __restrict__ edst,
    const float* __restrict__ coords, const float* __restrict__ P,
    const float* __restrict__ wc, const float* __restrict__ eb2,
    const float* __restrict__ w2pk, const float* __restrict__ c1pk,
    const float* __restrict__ cb1, const float* __restrict__ cw2) {
    extern __shared__ float sm[];
    float* As   = sm;                  // 4608
    float* Bs   = sm + 4608;           // 2 x 4096
    int* s_src  = (int*)(sm + 12800);
    int* s_dst  = (int*)(sm + 12928);
    float* s_ds = sm + 13056;
    float* s_wc = sm + 13184;
    float* s_eb2= sm + 13312;
    float* s_cb1= sm + 13440;
    float* s_cw2= sm + 13568;
    int tid = threadIdx.x, w = tid >> 5, lane = tid & 31;
    uint32_t bs_sm = (uint32_t)__cvta_generic_to_shared(Bs);
    int ebase = blockIdx.x * 128;

    auto cpB = [&](const float* src, int buf) {
        uint32_t dst = bs_sm + buf * 16384;
        #pragma unroll
        for (int j = 0; j < 4; j++)
            cp16(dst + (tid + j * 256) * 16, src + (tid + j * 256) * 4);
        CP_COMMIT();
    };

    cpB(w2pk, 0);                       // G0: B1 kb0

    if (tid < 128) {
        int e = ebase + tid;
        int s = esrc[e], d = edst[e];
        s_src[tid] = s; s_dst[tid] = d;
        float dx = coords[s * 3 + 0] - coords[d * 3 + 0];
        float dy = coords[s * 3 + 1] - coords[d * 3 + 1];
        float dz = coords[s * 3 + 2] - coords[d * 3 + 2];
        s_ds[tid] = dx * dx + dy * dy + dz * dz;
        s_wc[tid] = wc[tid];
        s_eb2[tid] = eb2[tid];
        s_cb1[tid] = cb1[tid];
        s_cw2[tid] = cw2[tid];
    }
    __syncthreads();

    float4 av[4];
    auto ldA1 = [&](int kb) {   // build A slice kb from P (LDG + silu into regs)
        #pragma unroll
        for (int i = 0; i < 4; i++) {
            int idx = tid + i * 256;
            int r = idx >> 3, c4 = idx & 7;
            int s = s_src[r], d = s_dst[r];
            float ds = s_ds[r];
            float4 ps = *(const float4*)(P + (size_t)s * 256 + kb * 32 + c4 * 4);
            float4 pd = *(const float4*)(P + (size_t)d * 256 + 128 + kb * 32 + c4 * 4);
            float4 wv = *(const float4*)(s_wc + kb * 32 + c4 * 4);
            float4 v;
            v.x = to_tf32(silu_f(ps.x + pd.x + ds * wv.x));
            v.y = to_tf32(silu_f(ps.y + pd.y + ds * wv.y));
            v.z = to_tf32(silu_f(ps.z + pd.z + ds * wv.z));
            v.w = to_tf32(silu_f(ps.w + pd.w + ds * wv.w));
            av[i] = v;
        }
    };
    auto ldA2 = [&](int kb) {   // reload m slice kb from g_M (already tf32)
        #pragma unroll
        for (int i = 0; i < 4; i++) {
            int idx = tid + i * 256;
            int r = idx >> 3, c4 = idx & 7;
            av[i] = *(const float4*)(g_M + (size_t)(ebase + r) * 128 + kb * 32 + c4 * 4);
        }
    };
    auto stA = [&]() {
        #pragma unroll
        for (int i = 0; i < 4; i++) {
            int idx = tid + i * 256;
            int r = idx >> 3, c4 = idx & 7;
            *(float4*)(As + r * 36 + c4 * 4) = av[i];
        }
    };

    float acc[16][4];
    #pragma unroll
    for (int nf = 0; nf < 16; nf++)
        #pragma unroll
        for (int j = 0; j < 4; j++) acc[nf][j] = 0.f;

    auto gemm_block = [&](const float* Bb) {
        #pragma unroll
        for (int ks = 0; ks < 4; ks++) {
            const float* ap = As + (w * 16 + (lane >> 2)) * 36 + ks * 8 + (lane & 3);
            uint32_t a0 = __float_as_uint(ap[0]);
            uint32_t a1 = __float_as_uint(ap[8 * 36]);
            uint32_t a2 = __float_as_uint(ap[4]);
            uint32_t a3 = __float_as_uint(ap[8 * 36 + 4]);
            #pragma unroll
            for (int nf = 0; nf < 16; nf++) {
                float2 b = *(const float2*)(Bb + ((nf * 4 + ks) * 32 + lane) * 2);
                mma_tf32(acc[nf], a0, a1, a2, a3,
                         __float_as_uint(b.x), __float_as_uint(b.y));
            }
        }
    };

    // ---- GEMM 1: pre @ eW2 ----
    ldA1(0);
    #pragma unroll
    for (int kb = 0; kb < 4; kb++) {
        stA();
        if (kb < 3) {
            cpB(w2pk + (size_t)(kb + 1) * 4096, (kb + 1) & 1);
            ldA1(kb + 1);
        } else {
            cpB(c1pk, 0);               // GEMM2 B kb0 -> buf0
        }
        CP_WAIT1();
        __syncthreads();
        gemm_block(Bs + (kb & 1) * 4096);
        __syncthreads();
    }

    // ---- epilogue 1: m = tf32(silu(.+eb2)) -> g_M; reset acc ----
    int r0 = w * 16 + (lane >> 2);
    int e0 = ebase + r0;
    #pragma unroll
    for (int nf = 0; nf < 16; nf++) {
        int col = nf * 8 + (lane & 3) * 2;
        float m0 = to_tf32(silu_f(acc[nf][0] + s_eb2[col]));
        float m1 = to_tf32(silu_f(acc[nf][1] + s_eb2[col + 1]));
        float m2 = to_tf32(silu_f(acc[nf][2] + s_eb2[col]));
        float m3 = to_tf32(silu_f(acc[nf][3] + s_eb2[col + 1]));
        *(float2*)(g_M + (size_t)e0 * 128 + col)       = make_float2(m0, m1);
        *(float2*)(g_M + (size_t)(e0 + 8) * 128 + col) = make_float2(m2, m3);
        acc[nf][0] = 0.f; acc[nf][1] = 0.f; acc[nf][2] = 0.f; acc[nf][3] = 0.f;
    }
    __syncthreads();     // STG g_M visible to all warps' LDG below

    // ---- GEMM 2: m @ cW1 (A via LDG from L2-hot g_M) ----
    ldA2(0);
    #pragma unroll
    for (int kb = 0; kb < 4; kb++) {
        stA();
        if (kb < 3) {
            cpB(c1pk + (size_t)(kb + 1) * 4096, (kb + 1) & 1);
            ldA2(kb + 1);
            CP_WAIT1();
        } else {
            CP_WAIT0();
        }
        __syncthreads();
        gemm_block(Bs + (kb & 1) * 4096);
        __syncthreads();
    }

    // ---- epilogue 2: gate = silu(.+cb1) . cw2 ----
    float g0 = 0.f, g1 = 0.f;
    #pragma unroll
    for (int nf = 0; nf < 16; nf++) {
        int col = nf * 8 + (lane & 3) * 2;
        g0 += silu_f(acc[nf][0] + s_cb1[col]) * s_cw2[col]
            + silu_f(acc[nf][1] + s_cb1[col + 1]) * s_cw2[col + 1];
        g1 += silu_f(acc[nf][2] + s_cb1[col]) * s_cw2[col]
            + silu_f(acc[nf][3] + s_cb1[col + 1]) * s_cw2[col + 1];
    }
    g0 += __shfl_xor_sync(0xffffffffu, g0, 1);
    g0 += __shfl_xor_sync(0xffffffffu, g0, 2);
    g1 += __shfl_xor_sync(0xffffffffu, g1, 1);
    g1 += __shfl_xor_sync(0xffffffffu, g1, 2);
    if ((lane & 3) == 0) {
        g_gate[e0]     = g0;
        g_gate[e0 + 8] = g1;
    }
}

// ================= shift accumulation =================
__global__ void shift_kernel(const int* __restrict__ esrc, const int* __restrict__ edst,
                             const float* __restrict__ coords) {
    int tid = threadIdx.x;
    int n = blockIdx.x * 4 + (tid >> 5);
    int lane = tid & 31;
    if (n >= NN) return;
    float sx = 0.f, sy = 0.f, sz = 0.f;
    if (lane < KNB) {
        int e = n * KNB + lane;
        int s = esrc[e], d = edst[e];
        float dx = coords[s * 3 + 0] - coords[d * 3 + 0];
        float dy = coords[s * 3 + 1] - coords[d * 3 + 1];
        float dz = coords[s * 3 + 2] - coords[d * 3 + 2];
        float dd = dx * dx + dy * dy + dz * dz;
        float gt = g_gate[e] * __frsqrt_rn(dd + 1e-8f);
        sx = dx * gt; sy = dy * gt; sz = dz * gt;
    }
    #pragma unroll
    for (int off = 8; off; off >>= 1) {
        sx += __shfl_down_sync(0xffffffffu, sx, off);
        sy += __shfl_down_sync(0xffffffffu, sy, off);
        sz += __shfl_down_sync(0xffffffffu, sz, off);
    }
    if (lane == 0) {
        g_shift[n * 3 + 0] += sx;
        g_shift[n * 3 + 1] += sy;
        g_shift[n * 3 + 2] += sz;
    }
}

__global__ void finalize_kernel(float* __restrict__ out) {
    int n = blockIdx.x, tid = threadIdx.x;
    out[NN * 3 + n * 128 + tid] = g_h[n * 128 + tid];
    if (tid < 3) out[n * 3 + tid] = g_shift[n * 3 + tid];
}

// ================= host =================
extern "C" void kernel_launch(void* const* d_in, const int* in_sizes, int n_in,
                              void* d_out, int out_size) {
    const float* z      = (const float*)d_in[0];
    const float* t      = (const float*)d_in[1];
    const float* coords = (const float*)d_in[2];
    const int*   species= (const int*)d_in[3];
    const int*   batch  = (const int*)d_in[4];
    const int*   esrc   = (const int*)d_in[5];
    const int*   edst   = (const int*)d_in[6];
    const float* spemb  = (const float*)d_in[7];
    const float* tmW1   = (const float*)d_in[8];
    const float* tmb1   = (const float*)d_in[9];
    const float* tmW2   = (const float*)d_in[10];
    const float* tmb2   = (const float*)d_in[11];
    const float* neW    = (const float*)d_in[12];
    const float* neb    = (const float*)d_in[13];
    const float* eW1    = (const float*)d_in[14];
    const float* eb1    = (const float*)d_in[15];
    const float* eW2    = (const float*)d_in[16];
    const float* eb2    = (const float*)d_in[17];
    const float* cW1    = (const float*)d_in[18];
    const float* cb1    = (const float*)d_in[19];
    const float* cW2    = (const float*)d_in[20];
    const float* nW1    = (const float*)d_in[21];
    const float* nb1    = (const float*)d_in[22];
    const float* nW2    = (const float*)d_in[23];
    const float* nb2    = (const float*)d_in[24];

    float *pX, *pP, *pU, *pH, *pM, *pPk, *pBiasP;
    cudaGetSymbolAddress((void**)&pX,    g_X);
    cudaGetSymbolAddress((void**)&pP,    g_P);
    cudaGetSymbolAddress((void**)&pU,    g_u);
    cudaGetSymbolAddress((void**)&pH,    g_h);
    cudaGetSymbolAddress((void**)&pM,    g_M);
    cudaGetSymbolAddress((void**)&pPk,   g_packW);
    cudaGetSymbolAddress((void**)&pBiasP, g_biasP);

    cudaFuncSetAttribute(mma_edge, cudaFuncAttributeMaxDynamicSharedMemorySize, EDGE_SMEM);
    cudaFuncSetAttribute(mma_node<1,1,false,false,true>,  cudaFuncAttributeMaxDynamicSharedMemorySize, NODE_SMEM1);
    cudaFuncSetAttribute(mma_node<2,0,false,false,false>, cudaFuncAttributeMaxDynamicSharedMemorySize, NODE_SMEM2);
    cudaFuncSetAttribute(mma_node<1,2,true,false,false>,  cudaFuncAttributeMaxDynamicSharedMemorySize, NODE_SMEM1);
    cudaFuncSetAttribute(mma_node<1,0,false,true,true>,   cudaFuncAttributeMaxDynamicSharedMemorySize, NODE_SMEM1);

    const int MT = (NN + 127) / 128;   // 157

    // launch 0: setup (pack + temb)
    setup_kernel<<<dim3(1024, 7), 256>>>(eW2, cW1, nW2, nW1, neW, eW1, eb1,
                                         t, tmW1, tmb1, tmW2, tmb2);
    // launch 1: h0 = [z|sp] @ neW + neb
    mma_node<1, 1, false, false, true><<<MT, 256, NODE_SMEM1>>>(
        z, spemb, nullptr, species, batch, 128,
        pPk + PK_NE, nullptr, neb, pH, 128, pX, 256, NN, 5, nullptr);

    for (int l = 0; l < NL; l++) {
        // P = [h|t] @ Wp  [launch 2 for l=0]
        mma_node<2, 0, false, false, false><<<MT, 256, NODE_SMEM2>>>(
            pX, nullptr, nullptr, nullptr, nullptr, 256,
            pPk + PK_WP + (l * 2 + 0) * 32768, pPk + PK_WP + (l * 2 + 1) * 32768,
            pBiasP + l * 256, pP, 256, nullptr, 0, NN, 8, nullptr);
        // fused edge: m + gate  [launch 3 for l=0 -> ncu capture]
        mma_edge<<<NE / 128, 256, EDGE_SMEM>>>(
            esrc, edst, coords, pP,
            eW1 + (size_t)l * 385 * 128 + 256 * 128, eb2 + l * 128,
            pPk + PK_EW2 + l * 16384, pPk + PK_CW1 + l * 16384,
            cb1 + l * 128, cW2 + l * 128);
        shift_kernel<<<(NN + 3) / 4, 128>>>(esrc, edst, coords);
        // u = silu([h | sum12 m | t] @ nW1 + nb1)
        mma_node<1, 2, true, false, false><<<MT, 256, NODE_SMEM1>>>(
            pH, pM, pX + 128, nullptr, nullptr, 0,
            pPk + PK_NW1 + l * 49152, nullptr, nb1 + l * 128,
            pU, 128, nullptr, 0, NN, 12, nullptr);
        // h = h + u @ nW2 + nb2
        mma_node<1, 0, false, true, true><<<MT, 256, NODE_SMEM1>>>(
            pU, nullptr, nullptr, nullptr, nullptr, 128,
            pPk + PK_NW2 + l * 16384, nullptr, nb2 + l * 128,
            pH, 128, pX, 256, NN, 4, pH);
    }

    finalize_kernel<<<NN, 128>>>((float*)d_out);
}

// round 8
// speedup vs baseline: 2.3506x; 1.0036x over previous
#include <cuda_runtime.h>
#include <math.h>
#include <stdint.h>

#define NN 20000
#define NG 400
#define KNB 12
#define NE 240000
#define NL 4

// ---- packed weight region offsets (floats) ----
#define PK_EW2 0
#define PK_CW1 65536
#define PK_NW2 131072
#define PK_NW1 196608
#define PK_NE  393216
#define PK_WP  413696
#define PK_TOTAL 675840

// ---- static device scratch ----
__device__ float g_temb[NG * 128];
__device__ float g_h[NN * 128];
__device__ float g_X[NN * 256];      // [h | t]
__device__ float g_P[NN * 256];
__device__ float g_M[NE * 128];      // tf32-rounded messages
__device__ float g_gate[NE];
__device__ float g_u[NN * 128];
__device__ float g_packW[PK_TOTAL];
__device__ float g_biasP[NL * 256];
__device__ float g_shift[NN * 3];

__device__ __forceinline__ float silu_f(float x) {
    return __fdividef(x, 1.0f + __expf(-x));
}
__device__ __forceinline__ float to_tf32(float x) {
    float r; asm("cvt.rna.tf32.f32 %0, %1;" : "=f"(r) : "f"(x)); return r;
}

__device__ __forceinline__ void mma_tf32(float c[4], uint32_t a0, uint32_t a1,
                                         uint32_t a2, uint32_t a3,
                                         uint32_t b0, uint32_t b1) {
    asm volatile(
        "mma.sync.aligned.m16n8k8.row.col.f32.tf32.tf32.f32 "
        "{%0,%1,%2,%3}, {%4,%5,%6,%7}, {%8,%9}, {%0,%1,%2,%3};"
        : "+f"(c[0]), "+f"(c[1]), "+f"(c[2]), "+f"(c[3])
        : "r"(a0), "r"(a1), "r"(a2), "r"(a3), "r"(b0), "r"(b1));
}

__device__ __forceinline__ void cp16(uint32_t saddr, const void* g) {
    asm volatile("cp.async.ca.shared.global [%0], [%1], 16;" :: "r"(saddr), "l"(g));
}
#define CP_COMMIT() asm volatile("cp.async.commit_group;" ::: "memory")
#define CP_WAIT1()  asm volatile("cp.async.wait_group 1;" ::: "memory")
#define CP_WAIT0()  asm volatile("cp.async.wait_group 0;" ::: "memory")

// B fragment layout per 32-K block (4096 floats), LDS.128-pairable:
//   pos = (nf*2 + (ks>>1))*128 + lane*4 + (ks&1)*2 + pair
//   k = kb*32 + ks*8 + (lane&3) + pair*4 ; n = nf*8 + (lane>>2)

// ================= launch 0: setup = pack (y<6) + temb (y==6) =================
__global__ void setup_kernel(const float* __restrict__ eW2, const float* __restrict__ cW1,
                             const float* __restrict__ nW2, const float* __restrict__ nW1,
                             const float* __restrict__ neW, const float* __restrict__ eW1,
                             const float* __restrict__ eb1,
                             const float* __restrict__ t,
                             const float* __restrict__ tmW1, const float* __restrict__ tmb1,
                             const float* __restrict__ tmW2, const float* __restrict__ tmb2) {
    int f = blockIdx.y;
    int tid = threadIdx.x;

    if (f == 6) {                       // ---- time-embedding MLP ----
        int g = blockIdx.x;
        if (g >= NG) return;
        __shared__ float e[128];
        __shared__ float hid[256];
        float tv = t[g];
        if (tid < 64) {
            float fr = expf(-(float)tid * (logf(10000.0f) / 63.0f));
            float a = tv * fr;
            e[tid] = sinf(a); e[tid + 64] = cosf(a);
        }
        __syncthreads();
        {
            float s = tmb1[tid];
            #pragma unroll 4
            for (int k = 0; k < 128; k++) s = fmaf(e[k], tmW1[k * 256 + tid], s);
            hid[tid] = silu_f(s);
        }
        __syncthreads();
        if (tid < 128) {
            float s = tmb2[tid];
            #pragma unroll 4
            for (int k = 0; k < 256; k++) s = fmaf(hid[k], tmW2[k * 128 + tid], s);
            g_temb[g * 128 + tid] = s;
        }
        return;
    }

    int i = blockIdx.x * 256 + tid;
    int kb, rr, dstbase;
    const float* src = nullptr;
    if (f <= 2) {
        if (i >= 65536) return;
        const float* W = (f == 0) ? eW2 : ((f == 1) ? cW1 : nW2);
        int l = i >> 14, r14 = i & 16383;
        kb = r14 >> 12; rr = r14 & 4095;
        src = W + (size_t)l * 16384;
        dstbase = ((f == 0) ? PK_EW2 : ((f == 1) ? PK_CW1 : PK_NW2)) + l * 16384;
    } else if (f == 3) {
        if (i >= 196608) return;
        int l = i / 49152, r = i % 49152;
        kb = r >> 12; rr = r & 4095;
        src = nW1 + (size_t)l * 49152;
        dstbase = PK_NW1 + l * 49152;
    } else if (f == 4) {
        if (i >= 20480) {
            if (i < 21504) {
                int idx2 = i - 20480;
                int l = idx2 >> 8, c = idx2 & 255;
                g_biasP[l * 256 + c] = (c < 128) ? eb1[l * 128 + c] : 0.f;
            }
            return;
        }
        kb = i >> 12; rr = i & 4095;
        src = neW;
        dstbase = PK_NE;
    } else {                            // f == 5: folded eW1 -> Wp
        if (i >= 262144) return;
        int l = i >> 16, r = i & 65535, slab = r >> 15, r2 = r & 32767;
        kb = r2 >> 12; rr = r2 & 4095;
        int hi = rr >> 7, lo = rr & 127;
        int nf = hi >> 1, ksh = hi & 1;
        int lane = lo >> 2, tb = lo & 3;
        int ks = ksh * 2 + (tb >> 1), pair = tb & 1;
        int k = kb * 32 + ks * 8 + (lane & 3) + pair * 4;
        int n = nf * 8 + (lane >> 2);
        const float* W = eW1 + (size_t)l * 385 * 128;
        float v;
        if (slab == 0) v = (k < 128) ? W[k * 128 + n] : W[(257 + (k - 128)) * 128 + n];
        else           v = (k < 128) ? W[(128 + k) * 128 + n] : 0.f;
        g_packW[PK_WP + (l * 2 + slab) * 32768 + kb * 4096 + rr] = to_tf32(v);
        return;
    }
    int hi = rr >> 7, lo = rr & 127;
    int nf = hi >> 1, ksh = hi & 1;
    int lane = lo >> 2, tb = lo & 3;
    int ks = ksh * 2 + (tb >> 1), pair = tb & 1;
    int k = kb * 32 + ks * 8 + (lane & 3) + pair * 4;
    int n = nf * 8 + (lane >> 2);
    g_packW[dstbase + kb * 4096 + rr] = to_tf32(src[(size_t)k * 128 + n]);
}

// ================= pipelined node GEMM =================
template <int NS, int MODE, bool SILU, bool RES, bool DUAL>
__global__ void __launch_bounds__(256) mma_node(
    const float* __restrict__ A0, const float* __restrict__ A1,
    const float* __restrict__ A2, const int* __restrict__ idxp,
    const int* __restrict__ batch, int ldA,
    const float* __restrict__ W0, const float* __restrict__ W1,
    const float* __restrict__ bias,
    float* __restrict__ C, int ldC, float* __restrict__ C2, int ldC2,
    int M, int Kb, const float* __restrict__ Rsrc) {
    extern __shared__ float sm[];
    float* As = sm;
    float* Bs = sm + 4608;
    float* s_bias = Bs + 2 * 4096 * NS;
    int tid = threadIdx.x, w = tid >> 5, lane = tid & 31;
    for (int i = tid; i < NS * 128; i += 256) s_bias[i] = bias[i];
    int m0 = blockIdx.x * 128;
    uint32_t bs_sm = (uint32_t)__cvta_generic_to_shared(Bs);

    if (MODE == 1) {
        for (int idx = tid; idx < 4096; idx += 256) {
            int r = idx >> 5, c4 = idx & 31;
            int row = m0 + r;
            if (row < NN) {
                float4 tv = *(const float4*)(g_temb + (size_t)batch[row] * 128 + c4 * 4);
                *(float4*)(g_X + (size_t)row * 256 + 128 + c4 * 4) = tv;
            }
        }
        if (tid < 128) {
            int row = m0 + tid;
            if (row < NN) {
                g_shift[row * 3 + 0] = 0.f;
                g_shift[row * 3 + 1] = 0.f;
                g_shift[row * 3 + 2] = 0.f;
            }
        }
    }

    float acc[NS][16][4];
    #pragma unroll
    for (int s = 0; s < NS; s++)
        #pragma unroll
        for (int nf = 0; nf < 16; nf++)
            #pragma unroll
            for (int j = 0; j < 4; j++) acc[s][nf][j] = 0.f;

    float4 av[4];
    auto ldA_regs = [&](int kb) {
        #pragma unroll
        for (int i = 0; i < 4; i++) {
            int idx = tid + i * 256;
            int r = idx >> 3, c4 = idx & 7;
            int row = m0 + r;
            float4 v = make_float4(0.f, 0.f, 0.f, 0.f);
            if (row < M) {
                if (MODE == 0) {
                    v = *(const float4*)(A0 + (size_t)row * ldA + kb * 32 + c4 * 4);
                } else if (MODE == 1) {
                    if (kb < 4) v = *(const float4*)(A0 + (size_t)row * 128 + kb * 32 + c4 * 4);
                    else        v = *(const float4*)(A1 + (size_t)idxp[row] * 32 + c4 * 4);
                } else {
                    if (kb < 4) {
                        v = *(const float4*)(A0 + (size_t)row * 128 + kb * 32 + c4 * 4);
                    } else if (kb < 8) {
                        const float* base = A1 + (size_t)row * KNB * 128 + (kb - 4) * 32 + c4 * 4;
                        #pragma unroll
                        for (int j = 0; j < KNB; j++) {
                            float4 mv = *(const float4*)(base + j * 128);
                            v.x += mv.x; v.y += mv.y; v.z += mv.z; v.w += mv.w;
                        }
                    } else {
                        v = *(const float4*)(A2 + (size_t)row * 256 + (kb - 8) * 32 + c4 * 4);
                    }
                }
            }
            av[i] = v;
        }
    };
    auto stA = [&]() {
        #pragma unroll
        for (int i = 0; i < 4; i++) {
            int idx = tid + i * 256;
            int r = idx >> 3, c4 = idx & 7;
            float4 v;
            v.x = to_tf32(av[i].x); v.y = to_tf32(av[i].y);
            v.z = to_tf32(av[i].z); v.w = to_tf32(av[i].w);
            *(float4*)(As + r * 36 + c4 * 4) = v;
        }
    };
    auto cpB = [&](int kb, int buf) {
        uint32_t dst = bs_sm + buf * (4096 * NS) * 4;
        const float* s0 = W0 + (size_t)kb * 4096;
        #pragma unroll
        for (int j = 0; j < 4; j++)
            cp16(dst + (tid + j * 256) * 16, s0 + (tid + j * 256) * 4);
        if constexpr (NS == 2) {
            const float* s1 = W1 + (size_t)kb * 4096;
            #pragma unroll
            for (int j = 0; j < 4; j++)
                cp16(dst + 16384 + (tid + j * 256) * 16, s1 + (tid + j * 256) * 4);
        }
        CP_COMMIT();
    };

    ldA_regs(0);
    cpB(0, 0);
    for (int kb = 0; kb < Kb; kb++) {
        int cur = kb & 1;
        stA();
        if (kb + 1 < Kb) {
            cpB(kb + 1, cur ^ 1);
            ldA_regs(kb + 1);
            CP_WAIT1();
        } else {
            CP_WAIT0();
        }
        __syncthreads();
        const float* Bb = Bs + cur * (4096 * NS);
        #pragma unroll
        for (int ksh = 0; ksh < 2; ksh++) {
            const float* ap = As + (w * 16 + (lane >> 2)) * 36 + ksh * 16 + (lane & 3);
            uint32_t p00 = __float_as_uint(ap[0]);
            uint32_t p01 = __float_as_uint(ap[8 * 36]);
            uint32_t p02 = __float_as_uint(ap[4]);
            uint32_t p03 = __float_as_uint(ap[8 * 36 + 4]);
            uint32_t p10 = __float_as_uint(ap[8]);
            uint32_t p11 = __float_as_uint(ap[8 * 36 + 8]);
            uint32_t p12 = __float_as_uint(ap[12]);
            uint32_t p13 = __float_as_uint(ap[8 * 36 + 12]);
            #pragma unroll
            for (int nf = 0; nf < 16; nf++) {
                float4 b = *(const float4*)(Bb + (nf * 2 + ksh) * 128 + lane * 4);
                mma_tf32(acc[0][nf], p00, p01, p02, p03,
                         __float_as_uint(b.x), __float_as_uint(b.y));
                mma_tf32(acc[0][nf], p10, p11, p12, p13,
                         __float_as_uint(b.z), __float_as_uint(b.w));
                if constexpr (NS == 2) {
                    float4 b1v = *(const float4*)(Bb + 4096 + (nf * 2 + ksh) * 128 + lane * 4);
                    mma_tf32(acc[1][nf], p00, p01, p02, p03,
                             __float_as_uint(b1v.x), __float_as_uint(b1v.y));
                    mma_tf32(acc[1][nf], p10, p11, p12, p13,
                             __float_as_uint(b1v.z), __float_as_uint(b1v.w));
                }
            }
        }
        __syncthreads();
    }

    int r0 = w * 16 + (lane >> 2);
    int row0 = m0 + r0, row1 = row0 + 8;
    #pragma unroll
    for (int s = 0; s < NS; s++) {
        #pragma unroll
        for (int nf = 0; nf < 16; nf++) {
            int lc = nf * 8 + (lane & 3) * 2;
            int col = s * 128 + lc;
            float v0 = acc[s][nf][0] + s_bias[col];
            float v1 = acc[s][nf][1] + s_bias[col + 1];
            float v2 = acc[s][nf][2] + s_bias[col];
            float v3 = acc[s][nf][3] + s_bias[col + 1];
            if (SILU) { v0 = silu_f(v0); v1 = silu_f(v1); v2 = silu_f(v2); v3 = silu_f(v3); }
            if (row0 < M) {
                if (RES) {
                    float2 r = *(const float2*)(Rsrc + (size_t)row0 * 128 + col);
                    v0 += r.x; v1 += r.y;
                }
                *(float2*)(C + (size_t)row0 * ldC + col) = make_float2(v0, v1);
                if (DUAL) *(float2*)(C2 + (size_t)row0 * ldC2 + col) = make_float2(v0, v1);
            }
            if (row1 < M) {
                if (RES) {
                    float2 r = *(const float2*)(Rsrc + (size_t)row1 * 128 + col);
                    v2 += r.x; v3 += r.y;
                }
                *(float2*)(C + (size_t)row1 * ldC + col) = make_float2(v2, v3);
                if (DUAL) *(float2*)(C2 + (size_t)row1 * ldC2 + col) = make_float2(v2, v3);
            }
        }
    }
}
#define NODE_SMEM1 51712
#define NODE_SMEM2 84992

// ================= fused edge kernel: 256 thr, 8 warps = 4 rowgrp x 2 colgrp =================
// smem floats: As[4608] | Bs[2][4096] | gate[256] | meta 896 -> 13952 fl = 55808 B
#define EDGE_SMEM 55808
__global__ void __launch_bounds__(256, 2) mma_edge(
    const int* __restrict__ esrc, const int* __restrict__ edst,
    const float* __restrict__ coords, const float* __restrict__ P,
    const float* __restrict__ wc, const float* __restrict__ eb2,
    const float* __restrict__ w2pk, const float* __restrict__ c1pk,
    const float* __restrict__ cb1, const float* __restrict__ cw2) {
    extern __shared__ float sm[];
    float* As     = sm;                  // 4608
    float* Bs     = sm + 4608;           // 2 x 4096
    float* s_gate = sm + 12800;          // 256
    int* s_src    = (int*)(sm + 13056);
    int* s_dst    = (int*)(sm + 13184);
    float* s_ds   = sm + 13312;
    float* s_wc   = sm + 13440;
    float* s_eb2  = sm + 13568;
    float* s_cb1  = sm + 13696;
    float* s_cw2  = sm + 13824;
    int tid = threadIdx.x, w = tid >> 5, lane = tid & 31;
    int wr = w & 3, cg = w >> 2;
    uint32_t bs_sm = (uint32_t)__cvta_generic_to_shared(Bs);
    int ebase = blockIdx.x * 128;

    auto cpB = [&](const float* src, int buf) {
        uint32_t dst = bs_sm + buf * 16384;
        #pragma unroll
        for (int j = 0; j < 4; j++)
            cp16(dst + (tid + j * 256) * 16, src + (tid + j * 256) * 4);
        CP_COMMIT();
    };

    cpB(w2pk, 0);                       // prefetch GEMM1 kb0

    if (tid < 128) {
        int e = ebase + tid;
        int s = esrc[e], d = edst[e];
        s_src[tid] = s; s_dst[tid] = d;
        float dx = coords[s * 3 + 0] - coords[d * 3 + 0];
        float dy = coords[s * 3 + 1] - coords[d * 3 + 1];
        float dz = coords[s * 3 + 2] - coords[d * 3 + 2];
        s_ds[tid] = dx * dx + dy * dy + dz * dz;
        s_wc[tid] = wc[tid];
        s_eb2[tid] = eb2[tid];
        s_cb1[tid] = cb1[tid];
        s_cw2[tid] = cw2[tid];
    }
    __syncthreads();

    float4 av[4];
    auto ldA1 = [&](int kb) {   // build A slice kb from P (LDG + silu into regs)
        #pragma unroll
        for (int i = 0; i < 4; i++) {
            int idx = tid + i * 256;
            int r = idx >> 3, c4 = idx & 7;
            int s = s_src[r], d = s_dst[r];
            float ds = s_ds[r];
            float4 ps = *(const float4*)(P + (size_t)s * 256 + kb * 32 + c4 * 4);
            float4 pd = *(const float4*)(P + (size_t)d * 256 + 128 + kb * 32 + c4 * 4);
            float4 wv = *(const float4*)(s_wc + kb * 32 + c4 * 4);
            float4 v;
            v.x = to_tf32(silu_f(ps.x + pd.x + ds * wv.x));
            v.y = to_tf32(silu_f(ps.y + pd.y + ds * wv.y));
            v.z = to_tf32(silu_f(ps.z + pd.z + ds * wv.z));
            v.w = to_tf32(silu_f(ps.w + pd.w + ds * wv.w));
            av[i] = v;
        }
    };
    auto ldA2 = [&](int kb) {   // reload m slice kb from g_M (already tf32)
        #pragma unroll
        for (int i = 0; i < 4; i++) {
            int idx = tid + i * 256;
            int r = idx >> 3, c4 = idx & 7;
            av[i] = *(const float4*)(g_M + (size_t)(ebase + r) * 128 + kb * 32 + c4 * 4);
        }
    };
    auto stA = [&]() {
        #pragma unroll
        for (int i = 0; i < 4; i++) {
            int idx = tid + i * 256;
            int r = idx >> 3, c4 = idx & 7;
            *(float4*)(As + r * 36 + c4 * 4) = av[i];
        }
    };

    float acc[2][8][4];
    #pragma unroll
    for (int mf = 0; mf < 2; mf++)
        #pragma unroll
        for (int nf = 0; nf < 8; nf++)
            #pragma unroll
            for (int j = 0; j < 4; j++) acc[mf][nf][j] = 0.f;

    auto gemm_block = [&](const float* Bb) {
        #pragma unroll
        for (int ksh = 0; ksh < 2; ksh++) {
            const float* ap = As + (wr * 32 + (lane >> 2)) * 36 + ksh * 16 + (lane & 3);
            uint32_t A0r[2][4], A1r[2][4];
            #pragma unroll
            for (int mf = 0; mf < 2; mf++) {
                const float* amp = ap + mf * 16 * 36;
                A0r[mf][0] = __float_as_uint(amp[0]);
                A0r[mf][1] = __float_as_uint(amp[8 * 36]);
                A0r[mf][2] = __float_as_uint(amp[4]);
                A0r[mf][3] = __float_as_uint(amp[8 * 36 + 4]);
                A1r[mf][0] = __float_as_uint(amp[8]);
                A1r[mf][1] = __float_as_uint(amp[8 * 36 + 8]);
                A1r[mf][2] = __float_as_uint(amp[12]);
                A1r[mf][3] = __float_as_uint(amp[8 * 36 + 12]);
            }
            #pragma unroll
            for (int nf = 0; nf < 8; nf++) {
                float4 b = *(const float4*)(Bb + ((cg * 8 + nf) * 2 + ksh) * 128 + lane * 4);
                #pragma unroll
                for (int mf = 0; mf < 2; mf++) {
                    mma_tf32(acc[mf][nf], A0r[mf][0], A0r[mf][1], A0r[mf][2], A0r[mf][3],
                             __float_as_uint(b.x), __float_as_uint(b.y));
                    mma_tf32(acc[mf][nf], A1r[mf][0], A1r[mf][1], A1r[mf][2], A1r[mf][3],
                             __float_as_uint(b.z), __float_as_uint(b.w));
                }
            }
        }
    };

    // ---- GEMM 1: pre @ eW2 ----
    ldA1(0);
    #pragma unroll
    for (int kb = 0; kb < 4; kb++) {
        stA();
        if (kb < 3) {
            cpB(w2pk + (size_t)(kb + 1) * 4096, (kb + 1) & 1);
            ldA1(kb + 1);
        } else {
            cpB(c1pk, 0);               // GEMM2 B kb0 -> buf0
        }
        CP_WAIT1();
        __syncthreads();
        gemm_block(Bs + (kb & 1) * 4096);
        __syncthreads();
    }

    // ---- epilogue 1: m = tf32(silu(.+eb2)) -> g_M; reset acc ----
    int r0 = wr * 32 + (lane >> 2);
    int e0 = ebase + r0;
    #pragma unroll
    for (int mf = 0; mf < 2; mf++) {
        int ea = e0 + mf * 16;
        #pragma unroll
        for (int nf = 0; nf < 8; nf++) {
            int col = cg * 64 + nf * 8 + (lane & 3) * 2;
            float m0 = to_tf32(silu_f(acc[mf][nf][0] + s_eb2[col]));
            float m1 = to_tf32(silu_f(acc[mf][nf][1] + s_eb2[col + 1]));
            float m2 = to_tf32(silu_f(acc[mf][nf][2] + s_eb2[col]));
            float m3 = to_tf32(silu_f(acc[mf][nf][3] + s_eb2[col + 1]));
            *(float2*)(g_M + (size_t)ea * 128 + col)       = make_float2(m0, m1);
            *(float2*)(g_M + (size_t)(ea + 8) * 128 + col) = make_float2(m2, m3);
            acc[mf][nf][0] = 0.f; acc[mf][nf][1] = 0.f;
            acc[mf][nf][2] = 0.f; acc[mf][nf][3] = 0.f;
        }
    }
    __syncthreads();     // STG g_M visible to all warps' LDG below

    // ---- GEMM 2: m @ cW1 (A via LDG from L2-hot g_M) ----
    ldA2(0);
    #pragma unroll
    for (int kb = 0; kb < 4; kb++) {
        stA();
        if (kb < 3) {
            cpB(c1pk + (size_t)(kb + 1) * 4096, (kb + 1) & 1);
            ldA2(kb + 1);
            CP_WAIT1();
        } else {
            CP_WAIT0();
        }
        __syncthreads();
        gemm_block(Bs + (kb & 1) * 4096);
        __syncthreads();
    }

    // ---- epilogue 2: gate partials -> smem, cross-colgroup combine ----
    float gp[4] = {0.f, 0.f, 0.f, 0.f};
    #pragma unroll
    for (int mf = 0; mf < 2; mf++) {
        #pragma unroll
        for (int nf = 0; nf < 8; nf++) {
            int col = cg * 64 + nf * 8 + (lane & 3) * 2;
            gp[mf * 2]     += silu_f(acc[mf][nf][0] + s_cb1[col]) * s_cw2[col]
                            + silu_f(acc[mf][nf][1] + s_cb1[col + 1]) * s_cw2[col + 1];
            gp[mf * 2 + 1] += silu_f(acc[mf][nf][2] + s_cb1[col]) * s_cw2[col]
                            + silu_f(acc[mf][nf][3] + s_cb1[col + 1]) * s_cw2[col + 1];
        }
    }
    #pragma unroll
    for (int j = 0; j < 4; j++) {
        gp[j] += __shfl_xor_sync(0xffffffffu, gp[j], 1);
        gp[j] += __shfl_xor_sync(0xffffffffu, gp[j], 2);
    }
    if ((lane & 3) == 0) {
        int rl = wr * 32 + (lane >> 2);
        s_gate[rl * 2 + cg]        = gp[0];
        s_gate[(rl + 8) * 2 + cg]  = gp[1];
        s_gate[(rl + 16) * 2 + cg] = gp[2];
        s_gate[(rl + 24) * 2 + cg] = gp[3];
    }
    __syncthreads();
    if (tid < 128) g_gate[ebase + tid] = s_gate[tid * 2] + s_gate[tid * 2 + 1];
}

// ================= shift accumulation =================
__global__ void shift_kernel(const int* __restrict__ esrc, const int* __restrict__ edst,
                             const float* __restrict__ coords) {
    int tid = threadIdx.x;
    int n = blockIdx.x * 4 + (tid >> 5);
    int lane = tid & 31;
    if (n >= NN) return;
    float sx = 0.f, sy = 0.f, sz = 0.f;
    if (lane < KNB) {
        int e = n * KNB + lane;
        int s = esrc[e], d = edst[e];
        float dx = coords[s * 3 + 0] - coords[d * 3 + 0];
        float dy = coords[s * 3 + 1] - coords[d * 3 + 1];
        float dz = coords[s * 3 + 2] - coords[d * 3 + 2];
        float dd = dx * dx + dy * dy + dz * dz;
        float gt = g_gate[e] * __frsqrt_rn(dd + 1e-8f);
        sx = dx * gt; sy = dy * gt; sz = dz * gt;
    }
    #pragma unroll
    for (int off = 8; off; off >>= 1) {
        sx += __shfl_down_sync(0xffffffffu, sx, off);
        sy += __shfl_down_sync(0xffffffffu, sy, off);
        sz += __shfl_down_sync(0xffffffffu, sz, off);
    }
    if (lane == 0) {
        g_shift[n * 3 + 0] += sx;
        g_shift[n * 3 + 1] += sy;
        g_shift[n * 3 + 2] += sz;
    }
}

__global__ void finalize_kernel(float* __restrict__ out) {
    int n = blockIdx.x, tid = threadIdx.x;
    out[NN * 3 + n * 128 + tid] = g_h[n * 128 + tid];
    if (tid < 3) out[n * 3 + tid] = g_shift[n * 3 + tid];
}

// ================= host =================
extern "C" void kernel_launch(void* const* d_in, const int* in_sizes, int n_in,
                              void* d_out, int out_size) {
    const float* z      = (const float*)d_in[0];
    const float* t      = (const float*)d_in[1];
    const float* coords = (const float*)d_in[2];
    const int*   species= (const int*)d_in[3];
    const int*   batch  = (const int*)d_in[4];
    const int*   esrc   = (const int*)d_in[5];
    const int*   edst   = (const int*)d_in[6];
    const float* spemb  = (const float*)d_in[7];
    const float* tmW1   = (const float*)d_in[8];
    const float* tmb1   = (const float*)d_in[9];
    const float* tmW2   = (const float*)d_in[10];
    const float* tmb2   = (const float*)d_in[11];
    const float* neW    = (const float*)d_in[12];
    const float* neb    = (const float*)d_in[13];
    const float* eW1    = (const float*)d_in[14];
    const float* eb1    = (const float*)d_in[15];
    const float* eW2    = (const float*)d_in[16];
    const float* eb2    = (const float*)d_in[17];
    const float* cW1    = (const float*)d_in[18];
    const float* cb1    = (const float*)d_in[19];
    const float* cW2    = (const float*)d_in[20];
    const float* nW1    = (const float*)d_in[21];
    const float* nb1    = (const float*)d_in[22];
    const float* nW2    = (const float*)d_in[23];
    const float* nb2    = (const float*)d_in[24];

    float *pX, *pP, *pU, *pH, *pM, *pPk, *pBiasP;
    cudaGetSymbolAddress((void**)&pX,    g_X);
    cudaGetSymbolAddress((void**)&pP,    g_P);
    cudaGetSymbolAddress((void**)&pU,    g_u);
    cudaGetSymbolAddress((void**)&pH,    g_h);
    cudaGetSymbolAddress((void**)&pM,    g_M);
    cudaGetSymbolAddress((void**)&pPk,   g_packW);
    cudaGetSymbolAddress((void**)&pBiasP, g_biasP);

    cudaFuncSetAttribute(mma_edge, cudaFuncAttributeMaxDynamicSharedMemorySize, EDGE_SMEM);
    cudaFuncSetAttribute(mma_node<1,1,false,false,true>,  cudaFuncAttributeMaxDynamicSharedMemorySize, NODE_SMEM1);
    cudaFuncSetAttribute(mma_node<2,0,false,false,false>, cudaFuncAttributeMaxDynamicSharedMemorySize, NODE_SMEM2);
    cudaFuncSetAttribute(mma_node<1,2,true,false,false>,  cudaFuncAttributeMaxDynamicSharedMemorySize, NODE_SMEM1);
    cudaFuncSetAttribute(mma_node<1,0,false,true,true>,   cudaFuncAttributeMaxDynamicSharedMemorySize, NODE_SMEM1);

    const int MT = (NN + 127) / 128;   // 157

    setup_kernel<<<dim3(1024, 7), 256>>>(eW2, cW1, nW2, nW1, neW, eW1, eb1,
                                         t, tmW1, tmb1, tmW2, tmb2);
    mma_node<1, 1, false, false, true><<<MT, 256, NODE_SMEM1>>>(
        z, spemb, nullptr, species, batch, 128,
        pPk + PK_NE, nullptr, neb, pH, 128, pX, 256, NN, 5, nullptr);

    for (int l = 0; l < NL; l++) {
        mma_node<2, 0, false, false, false><<<MT, 256, NODE_SMEM2>>>(
            pX, nullptr, nullptr, nullptr, nullptr, 256,
            pPk + PK_WP + (l * 2 + 0) * 32768, pPk + PK_WP + (l * 2 + 1) * 32768,
            pBiasP + l * 256, pP, 256, nullptr, 0, NN, 8, nullptr);
        mma_edge<<<NE / 128, 256, EDGE_SMEM>>>(
            esrc, edst, coords, pP,
            eW1 + (size_t)l * 385 * 128 + 256 * 128, eb2 + l * 128,
            pPk + PK_EW2 + l * 16384, pPk + PK_CW1 + l * 16384,
            cb1 + l * 128, cW2 + l * 128);
        shift_kernel<<<(NN + 3) / 4, 128>>>(esrc, edst, coords);
        mma_node<1, 2, true, false, false><<<MT, 256, NODE_SMEM1>>>(
            pH, pM, pX + 128, nullptr, nullptr, 0,
            pPk + PK_NW1 + l * 49152, nullptr, nb1 + l * 128,
            pU, 128, nullptr, 0, NN, 12, nullptr);
        mma_node<1, 0, false, true, true><<<MT, 256, NODE_SMEM1>>>(
            pU, nullptr, nullptr, nullptr, nullptr, 128,
            pPk + PK_NW2 + l * 16384, nullptr, nb2 + l * 128,
            pH, 128, pX, 256, NN, 4, pH);
    }

    finalize_kernel<<<NN, 128>>>((float*)d_out);
}